// round 10
// baseline (speedup 1.0000x reference)
#include <cuda_runtime.h>
#include <cuda_bf16.h>
#include <cstdint>
#include <math.h>

#define BB  2
#define LL  2048
#define DD  1024
#define HH  16
#define DHD 64
#define FFD 4096
#define MTOT (BB*LL)          // 4096 rows

// ---------------- scratch (static device globals; no allocation) -------------
__device__ float g_h [(size_t)MTOT*DD];    // pre-LN2 tensor (o@wo+bo+x)
__device__ float g_q [(size_t)MTOT*DD];
__device__ float g_k [(size_t)MTOT*DD];
__device__ float g_v [(size_t)MTOT*DD];
__device__ float g_o [(size_t)MTOT*DD];    // attention output
__device__ float g_ff[(size_t)MTOT*FFD];   // FFN hidden
__device__ float g_psum[BB*1024];
__device__ float g_psq [BB*1024];
__device__ float g_mu  [BB];
__device__ float g_rstd[BB];

// bf16 hi/lo activation scratch (sized for largest: ff 4096x4096)
__device__ __nv_bfloat16 g_ah[(size_t)MTOT*FFD];
__device__ __nv_bfloat16 g_al[(size_t)MTOT*FFD];
// bf16 hi/lo weights: wq@0, wk@1M, wv@2M, wo@3M, w1@4M(4M), w2@8M(4M)
#define WOFF_Q  ((size_t)0)
#define WOFF_K  ((size_t)1024*1024)
#define WOFF_V  ((size_t)2*1024*1024)
#define WOFF_O  ((size_t)3*1024*1024)
#define WOFF_1  ((size_t)4*1024*1024)
#define WOFF_2  ((size_t)8*1024*1024)
__device__ __nv_bfloat16 g_wh[(size_t)12*1024*1024];
__device__ __nv_bfloat16 g_wl[(size_t)12*1024*1024];

// ======================= PTX helpers (baseline ISA, no 'a' features) =========
__device__ __forceinline__ uint32_t smem_u32(const void* p) {
    uint32_t a;
    asm("{ .reg .u64 t; cvta.to.shared.u64 t, %1; cvt.u32.u64 %0, t; }" : "=r"(a) : "l"(p));
    return a;
}
#define SWZ128(o) ((o) ^ (((o) >> 3) & 0x70))

#define CP_ASYNC16(dst, src) \
    asm volatile("cp.async.cg.shared.global [%0], [%1], 16;" :: "r"(dst), "l"(src))
#define CP_COMMIT() asm volatile("cp.async.commit_group;" ::: "memory")
#define CP_WAIT(n)  asm volatile("cp.async.wait_group %0;" :: "n"(n) : "memory")

__device__ __forceinline__ void ldsm_x4(uint32_t* r, uint32_t addr) {
    asm volatile("ldmatrix.sync.aligned.m8n8.x4.shared.b16 {%0,%1,%2,%3}, [%4];"
        : "=r"(r[0]), "=r"(r[1]), "=r"(r[2]), "=r"(r[3]) : "r"(addr));
}
__device__ __forceinline__ void mma16816(float* c, const uint32_t* a, const uint32_t* b) {
    asm volatile(
        "mma.sync.aligned.m16n8k16.row.col.f32.bf16.bf16.f32 "
        "{%0,%1,%2,%3}, {%4,%5,%6,%7}, {%8,%9}, {%0,%1,%2,%3};"
        : "+f"(c[0]), "+f"(c[1]), "+f"(c[2]), "+f"(c[3])
        : "r"(a[0]), "r"(a[1]), "r"(a[2]), "r"(a[3]), "r"(b[0]), "r"(b[1]));
}

// ---------------- LayerNorm over (L,D) jointly per batch ---------------------
__global__ void ln_partial(const float* __restrict__ x) {
    int b = blockIdx.y, blk = blockIdx.x;
    const float4* xb = (const float4*)x + (size_t)b*(LL*DD/4) + (size_t)blk*512;
    float s = 0.f, sq = 0.f;
    for (int i = threadIdx.x; i < 512; i += 256) {
        float4 v = xb[i];
        s  += v.x + v.y + v.z + v.w;
        sq += v.x*v.x + v.y*v.y + v.z*v.z + v.w*v.w;
    }
    __shared__ float ss[256], ssq[256];
    ss[threadIdx.x] = s; ssq[threadIdx.x] = sq;
    __syncthreads();
    for (int st = 128; st > 0; st >>= 1) {
        if (threadIdx.x < st) { ss[threadIdx.x] += ss[threadIdx.x+st]; ssq[threadIdx.x] += ssq[threadIdx.x+st]; }
        __syncthreads();
    }
    if (threadIdx.x == 0) { g_psum[b*1024+blk] = ss[0]; g_psq[b*1024+blk] = ssq[0]; }
}

__global__ void ln_finalize() {
    int b = blockIdx.x, tid = threadIdx.x;
    float s = 0.f, sq = 0.f;
    for (int i = tid; i < 1024; i += 256) { s += g_psum[b*1024+i]; sq += g_psq[b*1024+i]; }
    __shared__ float ss[256], ssq[256];
    ss[tid] = s; ssq[tid] = sq;
    __syncthreads();
    for (int st = 128; st > 0; st >>= 1) {
        if (tid < st) { ss[tid] += ss[tid+st]; ssq[tid] += ssq[tid+st]; }
        __syncthreads();
    }
    if (tid == 0) {
        float n   = (float)LL * (float)DD;
        float mu  = ss[0] / n;
        float var = ssq[0] / n - mu*mu;
        g_mu[b]   = mu;
        g_rstd[b] = rsqrtf(var + 1e-5f);
    }
}

__device__ __forceinline__ uint32_t pack_hi(float a, float b, __nv_bfloat16& ha, __nv_bfloat16& hb) {
    ha = __float2bfloat16(a); hb = __float2bfloat16(b);
    return ((uint32_t)__bfloat16_as_ushort(hb) << 16) | (uint32_t)__bfloat16_as_ushort(ha);
}

// normalize + split into bf16 hi/lo
__global__ void ln_apply_split(const float* __restrict__ in,
                               __nv_bfloat16* __restrict__ hi, __nv_bfloat16* __restrict__ lo) {
    int i = blockIdx.x*256 + threadIdx.x;           // float4 index
    int b = (i >= (LL*DD/4)) ? 1 : 0;
    float mu = g_mu[b], r = g_rstd[b];
    float4 v = ((const float4*)in)[i];
    v.x = (v.x-mu)*r; v.y = (v.y-mu)*r; v.z = (v.z-mu)*r; v.w = (v.w-mu)*r;
    __nv_bfloat16 h0,h1,h2,h3;
    uint2 ph, pl;
    ph.x = pack_hi(v.x, v.y, h0, h1);
    ph.y = pack_hi(v.z, v.w, h2, h3);
    float r0 = v.x - __bfloat162float(h0), r1 = v.y - __bfloat162float(h1);
    float r2 = v.z - __bfloat162float(h2), r3 = v.w - __bfloat162float(h3);
    __nv_bfloat16 l0,l1,l2,l3;
    pl.x = pack_hi(r0, r1, l0, l1);
    pl.y = pack_hi(r2, r3, l2, l3);
    ((uint2*)hi)[i] = ph;
    ((uint2*)lo)[i] = pl;
}

// plain split fp32 -> bf16 hi/lo
__global__ void split_kernel(const float* __restrict__ in,
                             __nv_bfloat16* __restrict__ hi, __nv_bfloat16* __restrict__ lo, int n4) {
    int i = blockIdx.x*256 + threadIdx.x;
    if (i >= n4) return;
    float4 v = ((const float4*)in)[i];
    __nv_bfloat16 h0,h1,h2,h3;
    uint2 ph, pl;
    ph.x = pack_hi(v.x, v.y, h0, h1);
    ph.y = pack_hi(v.z, v.w, h2, h3);
    float r0 = v.x - __bfloat162float(h0), r1 = v.y - __bfloat162float(h1);
    float r2 = v.z - __bfloat162float(h2), r3 = v.w - __bfloat162float(h3);
    __nv_bfloat16 l0,l1,l2,l3;
    pl.x = pack_hi(r0, r1, l0, l1);
    pl.y = pack_hi(r2, r3, l2, l3);
    ((uint2*)hi)[i] = ph;
    ((uint2*)lo)[i] = pl;
}

// =============== mma.sync GEMM: C[m,n] = sum_k A[m,k]*W[n,k] (+bias,resid,relu)
// CTA tile 128x128, K-chunk 64 bf16, 3-stage cp.async pipeline.
// 3-split products: Ah*Bh + Ah*Bl + Al*Bh. 8 warps as 4(m) x 2(n); warp 32x64.
// Inner loop emits three passes of 16 INDEPENDENT MMAs to hide accumulator RAW.
#define STAGES 3
#define TILEB 16384                 // one 128x64 bf16 tile (128B rows)
#define STAGE_BYTES (4*TILEB)       // Ah, Al, Bh, Bl
#define MMG_SMEM (STAGES*STAGE_BYTES + 1024)

__device__ __forceinline__ void issue_chunk(
    uint32_t sslot,
    const __nv_bfloat16* a0, const __nv_bfloat16* a1,
    const __nv_bfloat16* b0, const __nv_bfloat16* b1,
    int K, int k0, int tid)
{
    #pragma unroll
    for (int it = 0; it < 4; it++) {
        int idx = it*256 + tid;
        int row = idx >> 3, s = idx & 7;
        uint32_t off = SWZ128((uint32_t)(row*128 + s*16));
        size_t go = (size_t)row*K + k0 + s*8;
        CP_ASYNC16(sslot + off,            a0 + go);
        CP_ASYNC16(sslot + TILEB + off,    a1 + go);
        CP_ASYNC16(sslot + 2*TILEB + off,  b0 + go);
        CP_ASYNC16(sslot + 3*TILEB + off,  b1 + go);
    }
}

__global__ __launch_bounds__(256) void mm_gemm(
    const __nv_bfloat16* __restrict__ Ah, const __nv_bfloat16* __restrict__ Al,
    const __nv_bfloat16* __restrict__ Bh, const __nv_bfloat16* __restrict__ Bl,
    const float* __restrict__ bias, const float* __restrict__ resid,
    float* __restrict__ C, int M, int N, int K, int relu)
{
    extern __shared__ char smraw[];
    char* smb = (char*)(((uintptr_t)smraw + 1023) & ~(uintptr_t)1023);
    uint32_t sbase = smem_u32(smb);

    const int tid  = threadIdx.x;
    const int warp = tid >> 5, lane = tid & 31;
    const int m0 = blockIdx.y * 128, n0 = blockIdx.x * 128;
    const int wm = (warp >> 1) * 32;      // warp m offset within CTA tile
    const int wn = (warp & 1) * 64;       // warp n offset

    const __nv_bfloat16* tA0 = Ah + (size_t)m0 * K;
    const __nv_bfloat16* tA1 = Al + (size_t)m0 * K;
    const __nv_bfloat16* tB0 = Bh + (size_t)n0 * K;
    const __nv_bfloat16* tB1 = Bl + (size_t)n0 * K;

    float acc[2][8][4];
    #pragma unroll
    for (int i = 0; i < 2; i++)
        #pragma unroll
        for (int j = 0; j < 8; j++)
            #pragma unroll
            for (int q = 0; q < 4; q++) acc[i][j][q] = 0.f;

    const int nch = K >> 6;
    // prologue: stages 0,1
    issue_chunk(sbase + 0*STAGE_BYTES, tA0, tA1, tB0, tB1, K, 0, tid);
    CP_COMMIT();
    issue_chunk(sbase + 1*STAGE_BYTES, tA0, tA1, tB0, tB1, K, 64, tid);
    CP_COMMIT();

    // per-thread ldmatrix address components (constant across ks/chunks)
    const int arow  = (lane & 7) + ((lane >> 3) & 1) * 8;   // A: mats 0/1=m0-15,k0; 2/3=k+16
    const int akoff = (lane >> 4) * 16;
    const int brow  = (lane & 7) + (lane >> 4) * 8;          // B: mats 0/1=n0-7; 2/3=n8-15
    const int bkoff = ((lane >> 3) & 1) * 16;

    for (int c = 0; c < nch; c++) {
        CP_WAIT(1);
        __syncthreads();
        int cn = c + STAGES - 1;
        if (cn < nch)
            issue_chunk(sbase + (cn % STAGES)*STAGE_BYTES, tA0, tA1, tB0, tB1, K, cn*64, tid);
        CP_COMMIT();

        uint32_t sl = sbase + (c % STAGES)*STAGE_BYTES;
        #pragma unroll
        for (int ks = 0; ks < 4; ks++) {
            // ---- load all operand fragments for this k-step ----
            uint32_t ah[2][4], al[2][4], bh[4][4], bl[4][4];
            #pragma unroll
            for (int mf = 0; mf < 2; mf++) {
                uint32_t off = SWZ128((uint32_t)((wm + mf*16 + arow)*128 + ks*32 + akoff));
                ldsm_x4(ah[mf], sl + off);
                ldsm_x4(al[mf], sl + TILEB + off);
            }
            #pragma unroll
            for (int g = 0; g < 4; g++) {
                uint32_t off = SWZ128((uint32_t)((wn + g*16 + brow)*128 + ks*32 + bkoff));
                ldsm_x4(bh[g], sl + 2*TILEB + off);
                ldsm_x4(bl[g], sl + 3*TILEB + off);
            }
            // ---- pass 1: ah*bh (16 independent MMAs) ----
            #pragma unroll
            for (int g = 0; g < 4; g++)
                #pragma unroll
                for (int mf = 0; mf < 2; mf++) {
                    mma16816(acc[mf][2*g],   ah[mf], bh[g]);
                    mma16816(acc[mf][2*g+1], ah[mf], bh[g] + 2);
                }
            // ---- pass 2: ah*bl (16 independent MMAs) ----
            #pragma unroll
            for (int g = 0; g < 4; g++)
                #pragma unroll
                for (int mf = 0; mf < 2; mf++) {
                    mma16816(acc[mf][2*g],   ah[mf], bl[g]);
                    mma16816(acc[mf][2*g+1], ah[mf], bl[g] + 2);
                }
            // ---- pass 3: al*bh (16 independent MMAs) ----
            #pragma unroll
            for (int g = 0; g < 4; g++)
                #pragma unroll
                for (int mf = 0; mf < 2; mf++) {
                    mma16816(acc[mf][2*g],   al[mf], bh[g]);
                    mma16816(acc[mf][2*g+1], al[mf], bh[g] + 2);
                }
        }
    }

    // epilogue: registers -> global, fused bias/resid/relu
    const int rbase = m0 + wm + (lane >> 2);
    const int cbase = n0 + wn + (lane & 3) * 2;
    #pragma unroll
    for (int nf = 0; nf < 8; nf++) {
        const int col = cbase + nf*8;
        float2 bv = *(const float2*)(bias + col);
        #pragma unroll
        for (int mf = 0; mf < 2; mf++) {
            int r0 = rbase + mf*16;
            #pragma unroll
            for (int half = 0; half < 2; half++) {
                int rr = r0 + half*8;
                float2 v;
                v.x = acc[mf][nf][half*2+0] + bv.x;
                v.y = acc[mf][nf][half*2+1] + bv.y;
                if (resid) {
                    float2 rv = *(const float2*)(resid + (size_t)rr*N + col);
                    v.x += rv.x; v.y += rv.y;
                }
                if (relu) { v.x = fmaxf(v.x, 0.f); v.y = fmaxf(v.y, 0.f); }
                *(float2*)(C + (size_t)rr*N + col) = v;
            }
        }
    }
}

// ---------------- attention: O = softmax(Q K^T * 0.25) V, per (b,h) ----------
#define TQS 68
#define TPS 65
#define TVS 68

__global__ __launch_bounds__(256) void attn_kernel(
    const float* __restrict__ Q, const float* __restrict__ Km,
    const float* __restrict__ V, float* __restrict__ O)
{
    extern __shared__ float smf[];
    float* Qt = smf;
    float* Kt = Qt + 64*TQS;
    float* Pt = Kt + 64*TQS;
    float* Vs = Pt + 64*TPS;

    const int tid = threadIdx.x;
    const int sx = tid & 15, sy = tid >> 4;
    const int q0 = blockIdx.x * 64;
    const int h  = blockIdx.y, b = blockIdx.z;
    const size_t base = ((size_t)b*LL)*DD + (size_t)h*DHD;
    const float* Qb = Q  + base + (size_t)q0*DD;
    const float* Kb = Km + base;
    const float* Vb = V  + base;

    #pragma unroll
    for (int t = tid; t < 1024; t += 256) {
        int row = t >> 4;
        int c4  = (t & 15) << 2;
        float4 v = *(const float4*)(Qb + (size_t)row*DD + c4);
        Qt[(c4+0)*TQS + row] = v.x;
        Qt[(c4+1)*TQS + row] = v.y;
        Qt[(c4+2)*TQS + row] = v.z;
        Qt[(c4+3)*TQS + row] = v.w;
    }

    float acc[4][4];
    #pragma unroll
    for (int i = 0; i < 4; i++)
        #pragma unroll
        for (int j = 0; j < 4; j++) acc[i][j] = 0.f;
    float mrow[4], lrow[4];
    #pragma unroll
    for (int i = 0; i < 4; i++) { mrow[i] = -1e30f; lrow[i] = 0.f; }

    for (int kt = 0; kt < LL; kt += 64) {
        __syncthreads();
        #pragma unroll
        for (int t = tid; t < 1024; t += 256) {
            int row = t >> 4;
            int c4  = (t & 15) << 2;
            float4 kv = *(const float4*)(Kb + (size_t)(kt+row)*DD + c4);
            Kt[(c4+0)*TQS + row] = kv.x;
            Kt[(c4+1)*TQS + row] = kv.y;
            Kt[(c4+2)*TQS + row] = kv.z;
            Kt[(c4+3)*TQS + row] = kv.w;
            float4 vv = *(const float4*)(Vb + (size_t)(kt+row)*DD + c4);
            *(float4*)&Vs[row*TVS + c4] = vv;
        }
        __syncthreads();

        float s[4][4];
        #pragma unroll
        for (int i = 0; i < 4; i++)
            #pragma unroll
            for (int j = 0; j < 4; j++) s[i][j] = 0.f;
        #pragma unroll 4
        for (int kk = 0; kk < 64; kk++) {
            float4 qa = *(const float4*)&Qt[kk*TQS + sy*4];
            float4 kb = *(const float4*)&Kt[kk*TQS + sx*4];
            float ra[4] = {qa.x,qa.y,qa.z,qa.w};
            float rb[4] = {kb.x,kb.y,kb.z,kb.w};
            #pragma unroll
            for (int i = 0; i < 4; i++)
                #pragma unroll
                for (int j = 0; j < 4; j++)
                    s[i][j] = fmaf(ra[i], rb[j], s[i][j]);
        }

        #pragma unroll
        for (int i = 0; i < 4; i++) {
            #pragma unroll
            for (int j = 0; j < 4; j++) s[i][j] *= 0.25f;
            float tm = fmaxf(fmaxf(s[i][0], s[i][1]), fmaxf(s[i][2], s[i][3]));
            #pragma unroll
            for (int off = 1; off < 16; off <<= 1)
                tm = fmaxf(tm, __shfl_xor_sync(0xffffffffu, tm, off));
            float mnew = fmaxf(mrow[i], tm);
            float corr = __expf(mrow[i] - mnew);
            float rsum = 0.f;
            float p[4];
            #pragma unroll
            for (int j = 0; j < 4; j++) { p[j] = __expf(s[i][j] - mnew); rsum += p[j]; }
            #pragma unroll
            for (int off = 1; off < 16; off <<= 1)
                rsum += __shfl_xor_sync(0xffffffffu, rsum, off);
            lrow[i] = lrow[i]*corr + rsum;
            mrow[i] = mnew;
            #pragma unroll
            for (int j = 0; j < 4; j++) {
                acc[i][j] *= corr;
                Pt[(sx*4+j)*TPS + sy*4+i] = p[j];
            }
        }
        __syncthreads();

        #pragma unroll 4
        for (int c = 0; c < 64; c++) {
            float4 vb = *(const float4*)&Vs[c*TVS + sx*4];
            float pa0 = Pt[c*TPS + sy*4+0];
            float pa1 = Pt[c*TPS + sy*4+1];
            float pa2 = Pt[c*TPS + sy*4+2];
            float pa3 = Pt[c*TPS + sy*4+3];
            acc[0][0] = fmaf(pa0, vb.x, acc[0][0]); acc[0][1] = fmaf(pa0, vb.y, acc[0][1]);
            acc[0][2] = fmaf(pa0, vb.z, acc[0][2]); acc[0][3] = fmaf(pa0, vb.w, acc[0][3]);
            acc[1][0] = fmaf(pa1, vb.x, acc[1][0]); acc[1][1] = fmaf(pa1, vb.y, acc[1][1]);
            acc[1][2] = fmaf(pa1, vb.z, acc[1][2]); acc[1][3] = fmaf(pa1, vb.w, acc[1][3]);
            acc[2][0] = fmaf(pa2, vb.x, acc[2][0]); acc[2][1] = fmaf(pa2, vb.y, acc[2][1]);
            acc[2][2] = fmaf(pa2, vb.z, acc[2][2]); acc[2][3] = fmaf(pa2, vb.w, acc[2][3]);
            acc[3][0] = fmaf(pa3, vb.x, acc[3][0]); acc[3][1] = fmaf(pa3, vb.y, acc[3][1]);
            acc[3][2] = fmaf(pa3, vb.z, acc[3][2]); acc[3][3] = fmaf(pa3, vb.w, acc[3][3]);
        }
    }

    float* Ob = O + base + (size_t)q0*DD;
    #pragma unroll
    for (int i = 0; i < 4; i++) {
        float inv = 1.0f / lrow[i];
        float4 o4 = make_float4(acc[i][0]*inv, acc[i][1]*inv, acc[i][2]*inv, acc[i][3]*inv);
        *(float4*)(Ob + (size_t)(sy*4+i)*DD + sx*4) = o4;
    }
}

static const int kAttSmem = (int)((2*64*TQS + 64*TPS + 64*TVS) * sizeof(float));

// ---------------- launcher ---------------------------------------------------
extern "C" void kernel_launch(void* const* d_in, const int* in_sizes, int n_in,
                              void* d_out, int out_size) {
    const float* x  = (const float*)d_in[0];
    const float* wq = (const float*)d_in[1];
    const float* bq = (const float*)d_in[2];
    const float* wk = (const float*)d_in[3];
    const float* bk = (const float*)d_in[4];
    const float* wv = (const float*)d_in[5];
    const float* bv = (const float*)d_in[6];
    const float* wo = (const float*)d_in[7];
    const float* bo = (const float*)d_in[8];
    const float* w1 = (const float*)d_in[9];
    const float* b1 = (const float*)d_in[10];
    const float* w2 = (const float*)d_in[11];
    const float* b2 = (const float*)d_in[12];
    float* out = (float*)d_out;

    cudaFuncSetAttribute((const void*)attn_kernel,
                         cudaFuncAttributeMaxDynamicSharedMemorySize, kAttSmem);
    cudaFuncSetAttribute((const void*)mm_gemm,
                         cudaFuncAttributeMaxDynamicSharedMemorySize, MMG_SMEM);

    void *ph, *pq, *pk, *pv, *po, *pff, *pah, *pal, *pwh, *pwl;
    cudaGetSymbolAddress(&ph,  g_h);
    cudaGetSymbolAddress(&pq,  g_q);
    cudaGetSymbolAddress(&pk,  g_k);
    cudaGetSymbolAddress(&pv,  g_v);
    cudaGetSymbolAddress(&po,  g_o);
    cudaGetSymbolAddress(&pff, g_ff);
    cudaGetSymbolAddress(&pah, g_ah);
    cudaGetSymbolAddress(&pal, g_al);
    cudaGetSymbolAddress(&pwh, g_wh);
    cudaGetSymbolAddress(&pwl, g_wl);
    float* h  = (float*)ph;
    float* q  = (float*)pq;
    float* k  = (float*)pk;
    float* v  = (float*)pv;
    float* o  = (float*)po;
    float* ff = (float*)pff;
    __nv_bfloat16* ah = (__nv_bfloat16*)pah;
    __nv_bfloat16* al = (__nv_bfloat16*)pal;
    __nv_bfloat16* wh = (__nv_bfloat16*)pwh;
    __nv_bfloat16* wl = (__nv_bfloat16*)pwl;

    dim3 gRed(1024, BB);
    dim3 gProj(DD/128,  MTOT/128);   // (8, 32)
    dim3 gFF1 (FFD/128, MTOT/128);   // (32, 32)
    dim3 gAtt (LL/64, HH, BB);

    // weight splits (hi/lo bf16), every launch — deterministic
    split_kernel<<<1024, 256>>>(wq, wh + WOFF_Q, wl + WOFF_Q, 262144);
    split_kernel<<<1024, 256>>>(wk, wh + WOFF_K, wl + WOFF_K, 262144);
    split_kernel<<<1024, 256>>>(wv, wh + WOFF_V, wl + WOFF_V, 262144);
    split_kernel<<<1024, 256>>>(wo, wh + WOFF_O, wl + WOFF_O, 262144);
    split_kernel<<<4096, 256>>>(w1, wh + WOFF_1, wl + WOFF_1, 1048576);
    split_kernel<<<4096, 256>>>(w2, wh + WOFF_2, wl + WOFF_2, 1048576);

    // LN1 -> bf16 hi/lo activations
    ln_partial<<<gRed, 256>>>(x);
    ln_finalize<<<BB, 256>>>();
    ln_apply_split<<<4096, 256>>>(x, ah, al);
    // QKV projections (warp MMA)
    mm_gemm<<<gProj, 256, MMG_SMEM>>>(ah, al, wh + WOFF_Q, wl + WOFF_Q, bq, nullptr, q, MTOT, DD, DD, 0);
    mm_gemm<<<gProj, 256, MMG_SMEM>>>(ah, al, wh + WOFF_K, wl + WOFF_K, bk, nullptr, k, MTOT, DD, DD, 0);
    mm_gemm<<<gProj, 256, MMG_SMEM>>>(ah, al, wh + WOFF_V, wl + WOFF_V, bv, nullptr, v, MTOT, DD, DD, 0);
    // attention (fp32 SIMT)
    attn_kernel<<<gAtt, 256, kAttSmem>>>(q, k, v, o);
    // output projection + residual(x) -> h
    split_kernel<<<4096, 256>>>(o, ah, al, 1048576);
    mm_gemm<<<gProj, 256, MMG_SMEM>>>(ah, al, wh + WOFF_O, wl + WOFF_O, bo, x, h, MTOT, DD, DD, 0);
    // LN2 -> bf16 hi/lo
    ln_partial<<<gRed, 256>>>(h);
    ln_finalize<<<BB, 256>>>();
    ln_apply_split<<<4096, 256>>>(h, ah, al);
    // FFN
    mm_gemm<<<gFF1, 256, MMG_SMEM>>>(ah, al, wh + WOFF_1, wl + WOFF_1, b1, nullptr, ff, MTOT, FFD, DD, 1);
    split_kernel<<<16384, 256>>>(ff, ah, al, 4194304);
    mm_gemm<<<gProj, 256, MMG_SMEM>>>(ah, al, wh + WOFF_2, wl + WOFF_2, b2, x, out, MTOT, DD, FFD, 0);
}

// round 11
// speedup vs baseline: 1.6845x; 1.6845x over previous
#include <cuda_runtime.h>
#include <cuda_bf16.h>
#include <cstdint>
#include <math.h>

#define BB  2
#define LL  2048
#define DD  1024
#define HH  16
#define DHD 64
#define FFD 4096
#define MTOT (BB*LL)          // 4096 rows

// ---------------- scratch (static device globals; no allocation) -------------
__device__ float g_h [(size_t)MTOT*DD];    // pre-LN2 tensor (o@wo+bo+x)
__device__ float g_psum[BB*1024];
__device__ float g_psq [BB*1024];
__device__ float g_mu  [BB];
__device__ float g_rstd[BB];

// bf16 hi/lo buffers
__device__ __nv_bfloat16 g_ah[(size_t)MTOT*DD];     // LN outputs (hi)
__device__ __nv_bfloat16 g_al[(size_t)MTOT*DD];     // LN outputs (lo)
__device__ __nv_bfloat16 g_fh[(size_t)MTOT*FFD];    // FFN hidden hi
__device__ __nv_bfloat16 g_fl[(size_t)MTOT*FFD];    // FFN hidden lo
__device__ __nv_bfloat16 g_qh[(size_t)MTOT*DD];
__device__ __nv_bfloat16 g_ql[(size_t)MTOT*DD];
__device__ __nv_bfloat16 g_kh[(size_t)MTOT*DD];
__device__ __nv_bfloat16 g_kl[(size_t)MTOT*DD];
__device__ __nv_bfloat16 g_vh[(size_t)MTOT*DD];
__device__ __nv_bfloat16 g_vl[(size_t)MTOT*DD];
__device__ __nv_bfloat16 g_oh[(size_t)MTOT*DD];
__device__ __nv_bfloat16 g_ol[(size_t)MTOT*DD];
// bf16 hi/lo weights: wq@0, wk@1M, wv@2M, wo@3M, w1@4M(4M), w2@8M(4M)
#define WOFF_Q  ((size_t)0)
#define WOFF_K  ((size_t)1024*1024)
#define WOFF_V  ((size_t)2*1024*1024)
#define WOFF_O  ((size_t)3*1024*1024)
#define WOFF_1  ((size_t)4*1024*1024)
#define WOFF_2  ((size_t)8*1024*1024)
__device__ __nv_bfloat16 g_wh[(size_t)12*1024*1024];
__device__ __nv_bfloat16 g_wl[(size_t)12*1024*1024];

// ======================= PTX helpers (baseline ISA, no 'a' features) =========
__device__ __forceinline__ uint32_t smem_u32(const void* p) {
    uint32_t a;
    asm("{ .reg .u64 t; cvta.to.shared.u64 t, %1; cvt.u32.u64 %0, t; }" : "=r"(a) : "l"(p));
    return a;
}
#define SWZ128(o) ((o) ^ (((o) >> 3) & 0x70))

#define CP_ASYNC16(dst, src) \
    asm volatile("cp.async.cg.shared.global [%0], [%1], 16;" :: "r"(dst), "l"(src))
#define CP_COMMIT() asm volatile("cp.async.commit_group;" ::: "memory")
#define CP_WAIT(n)  asm volatile("cp.async.wait_group %0;" :: "n"(n) : "memory")

__device__ __forceinline__ void ldsm_x4(uint32_t* r, uint32_t addr) {
    asm volatile("ldmatrix.sync.aligned.m8n8.x4.shared.b16 {%0,%1,%2,%3}, [%4];"
        : "=r"(r[0]), "=r"(r[1]), "=r"(r[2]), "=r"(r[3]) : "r"(addr));
}
__device__ __forceinline__ void ldsm_x4_t(uint32_t* r, uint32_t addr) {
    asm volatile("ldmatrix.sync.aligned.m8n8.x4.trans.shared.b16 {%0,%1,%2,%3}, [%4];"
        : "=r"(r[0]), "=r"(r[1]), "=r"(r[2]), "=r"(r[3]) : "r"(addr));
}
__device__ __forceinline__ void mma16816(float* c, const uint32_t* a, const uint32_t* b) {
    asm volatile(
        "mma.sync.aligned.m16n8k16.row.col.f32.bf16.bf16.f32 "
        "{%0,%1,%2,%3}, {%4,%5,%6,%7}, {%8,%9}, {%0,%1,%2,%3};"
        : "+f"(c[0]), "+f"(c[1]), "+f"(c[2]), "+f"(c[3])
        : "r"(a[0]), "r"(a[1]), "r"(a[2]), "r"(a[3]), "r"(b[0]), "r"(b[1]));
}
// pack two fp32 -> bf16x2 (lo = p0, hi = p1)
__device__ __forceinline__ uint32_t pack_bf2(float p0, float p1) {
    uint32_t d;
    asm("cvt.rn.bf16x2.f32 %0, %1, %2;" : "=r"(d) : "f"(p1), "f"(p0));
    return d;
}

// ---------------- LayerNorm over (L,D) jointly per batch ---------------------
__global__ void ln_partial(const float* __restrict__ x) {
    int b = blockIdx.y, blk = blockIdx.x;
    const float4* xb = (const float4*)x + (size_t)b*(LL*DD/4) + (size_t)blk*512;
    float s = 0.f, sq = 0.f;
    for (int i = threadIdx.x; i < 512; i += 256) {
        float4 v = xb[i];
        s  += v.x + v.y + v.z + v.w;
        sq += v.x*v.x + v.y*v.y + v.z*v.z + v.w*v.w;
    }
    __shared__ float ss[256], ssq[256];
    ss[threadIdx.x] = s; ssq[threadIdx.x] = sq;
    __syncthreads();
    for (int st = 128; st > 0; st >>= 1) {
        if (threadIdx.x < st) { ss[threadIdx.x] += ss[threadIdx.x+st]; ssq[threadIdx.x] += ssq[threadIdx.x+st]; }
        __syncthreads();
    }
    if (threadIdx.x == 0) { g_psum[b*1024+blk] = ss[0]; g_psq[b*1024+blk] = ssq[0]; }
}

__global__ void ln_finalize() {
    int b = blockIdx.x, tid = threadIdx.x;
    float s = 0.f, sq = 0.f;
    for (int i = tid; i < 1024; i += 256) { s += g_psum[b*1024+i]; sq += g_psq[b*1024+i]; }
    __shared__ float ss[256], ssq[256];
    ss[tid] = s; ssq[tid] = sq;
    __syncthreads();
    for (int st = 128; st > 0; st >>= 1) {
        if (tid < st) { ss[tid] += ss[tid+st]; ssq[tid] += ssq[tid+st]; }
        __syncthreads();
    }
    if (tid == 0) {
        float n   = (float)LL * (float)DD;
        float mu  = ss[0] / n;
        float var = ssq[0] / n - mu*mu;
        g_mu[b]   = mu;
        g_rstd[b] = rsqrtf(var + 1e-5f);
    }
}

__device__ __forceinline__ uint32_t pack_hi(float a, float b, __nv_bfloat16& ha, __nv_bfloat16& hb) {
    ha = __float2bfloat16(a); hb = __float2bfloat16(b);
    return ((uint32_t)__bfloat16_as_ushort(hb) << 16) | (uint32_t)__bfloat16_as_ushort(ha);
}

// normalize + split into bf16 hi/lo
__global__ void ln_apply_split(const float* __restrict__ in,
                               __nv_bfloat16* __restrict__ hi, __nv_bfloat16* __restrict__ lo) {
    int i = blockIdx.x*256 + threadIdx.x;           // float4 index
    int b = (i >= (LL*DD/4)) ? 1 : 0;
    float mu = g_mu[b], r = g_rstd[b];
    float4 v = ((const float4*)in)[i];
    v.x = (v.x-mu)*r; v.y = (v.y-mu)*r; v.z = (v.z-mu)*r; v.w = (v.w-mu)*r;
    __nv_bfloat16 h0,h1,h2,h3;
    uint2 ph, pl;
    ph.x = pack_hi(v.x, v.y, h0, h1);
    ph.y = pack_hi(v.z, v.w, h2, h3);
    float r0 = v.x - __bfloat162float(h0), r1 = v.y - __bfloat162float(h1);
    float r2 = v.z - __bfloat162float(h2), r3 = v.w - __bfloat162float(h3);
    __nv_bfloat16 l0,l1,l2,l3;
    pl.x = pack_hi(r0, r1, l0, l1);
    pl.y = pack_hi(r2, r3, l2, l3);
    ((uint2*)hi)[i] = ph;
    ((uint2*)lo)[i] = pl;
}

// plain split fp32 -> bf16 hi/lo (weights)
__global__ void split_kernel(const float* __restrict__ in,
                             __nv_bfloat16* __restrict__ hi, __nv_bfloat16* __restrict__ lo, int n4) {
    int i = blockIdx.x*256 + threadIdx.x;
    if (i >= n4) return;
    float4 v = ((const float4*)in)[i];
    __nv_bfloat16 h0,h1,h2,h3;
    uint2 ph, pl;
    ph.x = pack_hi(v.x, v.y, h0, h1);
    ph.y = pack_hi(v.z, v.w, h2, h3);
    float r0 = v.x - __bfloat162float(h0), r1 = v.y - __bfloat162float(h1);
    float r2 = v.z - __bfloat162float(h2), r3 = v.w - __bfloat162float(h3);
    __nv_bfloat16 l0,l1,l2,l3;
    pl.x = pack_hi(r0, r1, l0, l1);
    pl.y = pack_hi(r2, r3, l2, l3);
    ((uint2*)hi)[i] = ph;
    ((uint2*)lo)[i] = pl;
}

// =============== mma.sync GEMM: C[m,n] = sum_k A[m,k]*W[n,k] (+bias,resid,relu)
// CTA tile 128x128, K-chunk 64 bf16, 3-stage cp.async pipeline (R9 inner loop).
// Output: either fp32 C, or bf16 hi/lo split (Chi/Clo non-null).
#define STAGES 3
#define TILEB 16384                 // one 128x64 bf16 tile (128B rows)
#define STAGE_BYTES (4*TILEB)       // Ah, Al, Bh, Bl
#define MMG_SMEM (STAGES*STAGE_BYTES + 1024)

__device__ __forceinline__ void issue_chunk(
    uint32_t sslot,
    const __nv_bfloat16* a0, const __nv_bfloat16* a1,
    const __nv_bfloat16* b0, const __nv_bfloat16* b1,
    int K, int k0, int tid)
{
    #pragma unroll
    for (int it = 0; it < 4; it++) {
        int idx = it*256 + tid;
        int row = idx >> 3, s = idx & 7;
        uint32_t off = SWZ128((uint32_t)(row*128 + s*16));
        size_t go = (size_t)row*K + k0 + s*8;
        CP_ASYNC16(sslot + off,            a0 + go);
        CP_ASYNC16(sslot + TILEB + off,    a1 + go);
        CP_ASYNC16(sslot + 2*TILEB + off,  b0 + go);
        CP_ASYNC16(sslot + 3*TILEB + off,  b1 + go);
    }
}

__global__ __launch_bounds__(256) void mm_gemm(
    const __nv_bfloat16* __restrict__ Ah, const __nv_bfloat16* __restrict__ Al,
    const __nv_bfloat16* __restrict__ Bh, const __nv_bfloat16* __restrict__ Bl,
    const float* __restrict__ bias, const float* __restrict__ resid,
    float* __restrict__ C, __nv_bfloat16* __restrict__ Chi, __nv_bfloat16* __restrict__ Clo,
    int M, int N, int K, int relu)
{
    extern __shared__ char smraw[];
    char* smb = (char*)(((uintptr_t)smraw + 1023) & ~(uintptr_t)1023);
    uint32_t sbase = smem_u32(smb);

    const int tid  = threadIdx.x;
    const int warp = tid >> 5, lane = tid & 31;
    const int m0 = blockIdx.y * 128, n0 = blockIdx.x * 128;
    const int wm = (warp >> 1) * 32;
    const int wn = (warp & 1) * 64;

    const __nv_bfloat16* tA0 = Ah + (size_t)m0 * K;
    const __nv_bfloat16* tA1 = Al + (size_t)m0 * K;
    const __nv_bfloat16* tB0 = Bh + (size_t)n0 * K;
    const __nv_bfloat16* tB1 = Bl + (size_t)n0 * K;

    float acc[2][8][4];
    #pragma unroll
    for (int i = 0; i < 2; i++)
        #pragma unroll
        for (int j = 0; j < 8; j++)
            #pragma unroll
            for (int q = 0; q < 4; q++) acc[i][j][q] = 0.f;

    const int nch = K >> 6;
    issue_chunk(sbase + 0*STAGE_BYTES, tA0, tA1, tB0, tB1, K, 0, tid);
    CP_COMMIT();
    issue_chunk(sbase + 1*STAGE_BYTES, tA0, tA1, tB0, tB1, K, 64, tid);
    CP_COMMIT();

    const int arow  = (lane & 7) + ((lane >> 3) & 1) * 8;
    const int akoff = (lane >> 4) * 16;
    const int brow  = (lane & 7) + (lane >> 4) * 8;
    const int bkoff = ((lane >> 3) & 1) * 16;

    for (int c = 0; c < nch; c++) {
        CP_WAIT(1);
        __syncthreads();
        int cn = c + STAGES - 1;
        if (cn < nch)
            issue_chunk(sbase + (cn % STAGES)*STAGE_BYTES, tA0, tA1, tB0, tB1, K, cn*64, tid);
        CP_COMMIT();

        uint32_t sl = sbase + (c % STAGES)*STAGE_BYTES;
        #pragma unroll
        for (int ks = 0; ks < 4; ks++) {
            uint32_t ah[2][4], al[2][4];
            #pragma unroll
            for (int mf = 0; mf < 2; mf++) {
                uint32_t off = SWZ128((uint32_t)((wm + mf*16 + arow)*128 + ks*32 + akoff));
                ldsm_x4(ah[mf], sl + off);
                ldsm_x4(al[mf], sl + TILEB + off);
            }
            #pragma unroll
            for (int g = 0; g < 4; g++) {
                uint32_t bh[4], bl[4];
                uint32_t off = SWZ128((uint32_t)((wn + g*16 + brow)*128 + ks*32 + bkoff));
                ldsm_x4(bh, sl + 2*TILEB + off);
                ldsm_x4(bl, sl + 3*TILEB + off);
                #pragma unroll
                for (int mf = 0; mf < 2; mf++) {
                    mma16816(acc[mf][2*g],   ah[mf], bh);
                    mma16816(acc[mf][2*g],   ah[mf], bl);
                    mma16816(acc[mf][2*g],   al[mf], bh);
                    mma16816(acc[mf][2*g+1], ah[mf], bh + 2);
                    mma16816(acc[mf][2*g+1], ah[mf], bl + 2);
                    mma16816(acc[mf][2*g+1], al[mf], bh + 2);
                }
            }
        }
    }

    // epilogue
    const int rbase = m0 + wm + (lane >> 2);
    const int cbase = n0 + wn + (lane & 3) * 2;
    #pragma unroll
    for (int nf = 0; nf < 8; nf++) {
        const int col = cbase + nf*8;
        float2 bv = *(const float2*)(bias + col);
        #pragma unroll
        for (int mf = 0; mf < 2; mf++) {
            int r0 = rbase + mf*16;
            #pragma unroll
            for (int half = 0; half < 2; half++) {
                int rr = r0 + half*8;
                float vx = acc[mf][nf][half*2+0] + bv.x;
                float vy = acc[mf][nf][half*2+1] + bv.y;
                if (resid) {
                    float2 rv = *(const float2*)(resid + (size_t)rr*N + col);
                    vx += rv.x; vy += rv.y;
                }
                if (relu) { vx = fmaxf(vx, 0.f); vy = fmaxf(vy, 0.f); }
                if (Chi) {
                    __nv_bfloat16 hx = __float2bfloat16(vx), hy = __float2bfloat16(vy);
                    float lx = vx - __bfloat162float(hx), ly = vy - __bfloat162float(hy);
                    uint32_t ph = ((uint32_t)__bfloat16_as_ushort(hy) << 16) | (uint32_t)__bfloat16_as_ushort(hx);
                    __nv_bfloat16 gx = __float2bfloat16(lx), gy = __float2bfloat16(ly);
                    uint32_t pl = ((uint32_t)__bfloat16_as_ushort(gy) << 16) | (uint32_t)__bfloat16_as_ushort(gx);
                    *(uint32_t*)(Chi + (size_t)rr*N + col) = ph;
                    *(uint32_t*)(Clo + (size_t)rr*N + col) = pl;
                } else {
                    float2 v2 = make_float2(vx, vy);
                    *(float2*)(C + (size_t)rr*N + col) = v2;
                }
            }
        }
    }
}

// ======= tensor-core flash attention: O = softmax(Q K^T * 0.25) V ============
// CTA: 128 q-rows of one (b,h). 8 warps x 16 rows. Key tiles of 64.
// S = QhKh + QhKl + QlKh (3-pass), PV = P(Vh) + P(Vl) (2-pass), fp32 softmax.
// smem: Q (qh,ql) 32KB + 2 stages x (kh,kl,vh,vl) 32KB = 96KB.
#define ATT_Q_BYTES 32768
#define ATT_KV_STAGE 32768
#define ATT_SMEM (ATT_Q_BYTES + 2*ATT_KV_STAGE)

__device__ __forceinline__ void attn_issue_kv(
    uint32_t kvs,
    const __nv_bfloat16* kh, const __nv_bfloat16* kl,
    const __nv_bfloat16* vh, const __nv_bfloat16* vl,
    size_t gbase, int tid)
{
    #pragma unroll
    for (int t = 0; t < 2; t++) {
        int idx = t*256 + tid;
        int row = idx >> 3, seg = idx & 7;
        uint32_t off = SWZ128((uint32_t)(row*128 + seg*16));
        size_t go = gbase + (size_t)row*DD + seg*8;
        CP_ASYNC16(kvs + off,          kh + go);
        CP_ASYNC16(kvs + 8192 + off,   kl + go);
        CP_ASYNC16(kvs + 16384 + off,  vh + go);
        CP_ASYNC16(kvs + 24576 + off,  vl + go);
    }
}

__global__ __launch_bounds__(256) void attn_tc(
    const __nv_bfloat16* __restrict__ qh, const __nv_bfloat16* __restrict__ ql,
    const __nv_bfloat16* __restrict__ kh, const __nv_bfloat16* __restrict__ kl,
    const __nv_bfloat16* __restrict__ vh, const __nv_bfloat16* __restrict__ vl,
    __nv_bfloat16* __restrict__ oh, __nv_bfloat16* __restrict__ ol)
{
    extern __shared__ char smraw[];
    uint32_t sb = smem_u32(smraw);
    const int tid = threadIdx.x, warp = tid >> 5, lane = tid & 31;
    const int qt = blockIdx.x;
    const int b = blockIdx.y >> 4, h = blockIdx.y & 15;
    const int wm = warp * 16;

    const size_t qbase  = ((size_t)(b*LL + qt*128))*DD + (size_t)h*DHD;
    const size_t kvbase = ((size_t)(b*LL))*DD + (size_t)h*DHD;

    // prologue: Q (both splits) + KV tile 0 -> one group
    #pragma unroll
    for (int t = 0; t < 4; t++) {
        int idx = t*256 + tid;
        int row = idx >> 3, seg = idx & 7;
        uint32_t off = SWZ128((uint32_t)(row*128 + seg*16));
        size_t go = qbase + (size_t)row*DD + seg*8;
        CP_ASYNC16(sb + off,          qh + go);
        CP_ASYNC16(sb + 16384 + off,  ql + go);
    }
    attn_issue_kv(sb + ATT_Q_BYTES, kh, kl, vh, vl, kvbase, tid);
    CP_COMMIT();

    float sO[8][4];
    #pragma unroll
    for (int j = 0; j < 8; j++)
        #pragma unroll
        for (int q = 0; q < 4; q++) sO[j][q] = 0.f;
    float mrow[2] = {-1e30f, -1e30f};
    float lrow[2] = {0.f, 0.f};

    const int arow  = (lane & 7) + ((lane >> 3) & 1) * 8;
    const int akoff = (lane >> 4) * 16;
    const int brow  = (lane & 7) + (lane >> 4) * 8;
    const int bkoff = ((lane >> 3) & 1) * 16;
    const int vgrp  = lane >> 3, vr = lane & 7;   // trans-ldsm addressing

    const int NT = LL / 64;   // 32 key tiles
    for (int kt = 0; kt < NT; kt++) {
        __syncthreads();   // everyone done computing previous tile
        if (kt + 1 < NT) {
            attn_issue_kv(sb + ATT_Q_BYTES + ((kt+1)&1)*ATT_KV_STAGE,
                          kh, kl, vh, vl, kvbase + (size_t)(kt+1)*64*DD, tid);
            CP_COMMIT();
            CP_WAIT(1);
        } else {
            CP_WAIT(0);
        }
        __syncthreads();

        uint32_t kvs = sb + ATT_Q_BYTES + (kt&1)*ATT_KV_STAGE;

        // ---- S = Q K^T (3-pass split) ----
        float sS[8][4];
        #pragma unroll
        for (int j = 0; j < 8; j++)
            #pragma unroll
            for (int q = 0; q < 4; q++) sS[j][q] = 0.f;

        #pragma unroll
        for (int ks = 0; ks < 4; ks++) {
            uint32_t aqh[4], aql[4];
            uint32_t offa = SWZ128((uint32_t)((wm + arow)*128 + ks*32 + akoff));
            ldsm_x4(aqh, sb + offa);
            ldsm_x4(aql, sb + 16384 + offa);
            #pragma unroll
            for (int g = 0; g < 4; g++) {
                uint32_t bh_[4], bl_[4];
                uint32_t offb = SWZ128((uint32_t)((g*16 + brow)*128 + ks*32 + bkoff));
                ldsm_x4(bh_, kvs + offb);
                ldsm_x4(bl_, kvs + 8192 + offb);
                mma16816(sS[2*g],   aqh, bh_);
                mma16816(sS[2*g],   aqh, bl_);
                mma16816(sS[2*g],   aql, bh_);
                mma16816(sS[2*g+1], aqh, bh_ + 2);
                mma16816(sS[2*g+1], aqh, bl_ + 2);
                mma16816(sS[2*g+1], aql, bh_ + 2);
            }
        }

        // scale (faithful source bug: 1/sqrt(H) = 0.25)
        #pragma unroll
        for (int j = 0; j < 8; j++)
            #pragma unroll
            for (int q = 0; q < 4; q++) sS[j][q] *= 0.25f;

        // ---- online softmax (rows: rr=0 -> lane>>2, rr=1 -> +8) ----
        #pragma unroll
        for (int rr = 0; rr < 2; rr++) {
            float tm = -1e30f;
            #pragma unroll
            for (int j = 0; j < 8; j++) {
                tm = fmaxf(tm, sS[j][rr*2+0]);
                tm = fmaxf(tm, sS[j][rr*2+1]);
            }
            tm = fmaxf(tm, __shfl_xor_sync(0xffffffffu, tm, 1));
            tm = fmaxf(tm, __shfl_xor_sync(0xffffffffu, tm, 2));
            float mnew = fmaxf(mrow[rr], tm);
            float corr = __expf(mrow[rr] - mnew);
            mrow[rr] = mnew;
            float psum = 0.f;
            #pragma unroll
            for (int j = 0; j < 8; j++) {
                float p0 = __expf(sS[j][rr*2+0] - mnew);
                float p1 = __expf(sS[j][rr*2+1] - mnew);
                sS[j][rr*2+0] = p0; sS[j][rr*2+1] = p1;
                psum += p0 + p1;
            }
            psum += __shfl_xor_sync(0xffffffffu, psum, 1);
            psum += __shfl_xor_sync(0xffffffffu, psum, 2);
            lrow[rr] = lrow[rr]*corr + psum;
            #pragma unroll
            for (int j = 0; j < 8; j++) {
                sO[j][rr*2+0] *= corr;
                sO[j][rr*2+1] *= corr;
            }
        }

        // ---- pack P (A-fragments for PV) ----
        uint32_t pa[4][4];
        #pragma unroll
        for (int k = 0; k < 4; k++) {
            pa[k][0] = pack_bf2(sS[2*k][0],   sS[2*k][1]);
            pa[k][1] = pack_bf2(sS[2*k][2],   sS[2*k][3]);
            pa[k][2] = pack_bf2(sS[2*k+1][0], sS[2*k+1][1]);
            pa[k][3] = pack_bf2(sS[2*k+1][2], sS[2*k+1][3]);
        }

        // ---- O += P V (2-pass: vh + vl) ----
        #pragma unroll
        for (int ks = 0; ks < 4; ks++) {
            #pragma unroll
            for (int g = 0; g < 4; g++) {
                uint32_t bvh[4], bvl[4];
                int row = ks*16 + (vgrp & 1)*8 + vr;
                int colb = (g*16 + (vgrp >> 1)*8) * 2;
                uint32_t offv = SWZ128((uint32_t)(row*128 + colb));
                ldsm_x4_t(bvh, kvs + 16384 + offv);
                ldsm_x4_t(bvl, kvs + 24576 + offv);
                mma16816(sO[2*g],   pa[ks], bvh);
                mma16816(sO[2*g],   pa[ks], bvl);
                mma16816(sO[2*g+1], pa[ks], bvh + 2);
                mma16816(sO[2*g+1], pa[ks], bvl + 2);
            }
        }
    }

    // ---- epilogue: normalize + bf16 hi/lo split store ----
    #pragma unroll
    for (int rr = 0; rr < 2; rr++) {
        float inv = 1.0f / lrow[rr];
        int row = qt*128 + wm + rr*8 + (lane >> 2);
        size_t ob = ((size_t)(b*LL + row))*DD + (size_t)h*DHD + (lane & 3)*2;
        #pragma unroll
        for (int j = 0; j < 8; j++) {
            float v0 = sO[j][rr*2+0] * inv;
            float v1 = sO[j][rr*2+1] * inv;
            __nv_bfloat16 h0 = __float2bfloat16(v0), h1 = __float2bfloat16(v1);
            float l0 = v0 - __bfloat162float(h0), l1 = v1 - __bfloat162float(h1);
            uint32_t ph = ((uint32_t)__bfloat16_as_ushort(h1) << 16) | (uint32_t)__bfloat16_as_ushort(h0);
            __nv_bfloat16 g0 = __float2bfloat16(l0), g1 = __float2bfloat16(l1);
            uint32_t pl = ((uint32_t)__bfloat16_as_ushort(g1) << 16) | (uint32_t)__bfloat16_as_ushort(g0);
            *(uint32_t*)(oh + ob + j*8) = ph;
            *(uint32_t*)(ol + ob + j*8) = pl;
        }
    }
}

// ---------------- launcher ---------------------------------------------------
extern "C" void kernel_launch(void* const* d_in, const int* in_sizes, int n_in,
                              void* d_out, int out_size) {
    const float* x  = (const float*)d_in[0];
    const float* wq = (const float*)d_in[1];
    const float* bq = (const float*)d_in[2];
    const float* wk = (const float*)d_in[3];
    const float* bk = (const float*)d_in[4];
    const float* wv = (const float*)d_in[5];
    const float* bv = (const float*)d_in[6];
    const float* wo = (const float*)d_in[7];
    const float* bo = (const float*)d_in[8];
    const float* w1 = (const float*)d_in[9];
    const float* b1 = (const float*)d_in[10];
    const float* w2 = (const float*)d_in[11];
    const float* b2 = (const float*)d_in[12];
    float* out = (float*)d_out;

    cudaFuncSetAttribute((const void*)mm_gemm,
                         cudaFuncAttributeMaxDynamicSharedMemorySize, MMG_SMEM);
    cudaFuncSetAttribute((const void*)attn_tc,
                         cudaFuncAttributeMaxDynamicSharedMemorySize, ATT_SMEM);

    void *ph_, *pah, *pal, *pfh, *pfl, *pwh, *pwl;
    void *pqh, *pql, *pkh, *pkl, *pvh, *pvl, *poh, *pol;
    cudaGetSymbolAddress(&ph_, g_h);
    cudaGetSymbolAddress(&pah, g_ah);
    cudaGetSymbolAddress(&pal, g_al);
    cudaGetSymbolAddress(&pfh, g_fh);
    cudaGetSymbolAddress(&pfl, g_fl);
    cudaGetSymbolAddress(&pwh, g_wh);
    cudaGetSymbolAddress(&pwl, g_wl);
    cudaGetSymbolAddress(&pqh, g_qh);
    cudaGetSymbolAddress(&pql, g_ql);
    cudaGetSymbolAddress(&pkh, g_kh);
    cudaGetSymbolAddress(&pkl, g_kl);
    cudaGetSymbolAddress(&pvh, g_vh);
    cudaGetSymbolAddress(&pvl, g_vl);
    cudaGetSymbolAddress(&poh, g_oh);
    cudaGetSymbolAddress(&pol, g_ol);
    float* h = (float*)ph_;
    __nv_bfloat16* ah = (__nv_bfloat16*)pah;
    __nv_bfloat16* al = (__nv_bfloat16*)pal;
    __nv_bfloat16* fh = (__nv_bfloat16*)pfh;
    __nv_bfloat16* fl = (__nv_bfloat16*)pfl;
    __nv_bfloat16* wh = (__nv_bfloat16*)pwh;
    __nv_bfloat16* wl = (__nv_bfloat16*)pwl;
    __nv_bfloat16* qh = (__nv_bfloat16*)pqh;
    __nv_bfloat16* ql = (__nv_bfloat16*)pql;
    __nv_bfloat16* kh = (__nv_bfloat16*)pkh;
    __nv_bfloat16* kl = (__nv_bfloat16*)pkl;
    __nv_bfloat16* vh = (__nv_bfloat16*)pvh;
    __nv_bfloat16* vl = (__nv_bfloat16*)pvl;
    __nv_bfloat16* oh = (__nv_bfloat16*)poh;
    __nv_bfloat16* ol = (__nv_bfloat16*)pol;

    dim3 gRed(1024, BB);
    dim3 gProj(DD/128,  MTOT/128);   // (8, 32)
    dim3 gFF1 (FFD/128, MTOT/128);   // (32, 32)
    dim3 gAtt (LL/128, BB*HH);       // (16, 32)

    // weight splits (hi/lo bf16), every launch — deterministic
    split_kernel<<<1024, 256>>>(wq, wh + WOFF_Q, wl + WOFF_Q, 262144);
    split_kernel<<<1024, 256>>>(wk, wh + WOFF_K, wl + WOFF_K, 262144);
    split_kernel<<<1024, 256>>>(wv, wh + WOFF_V, wl + WOFF_V, 262144);
    split_kernel<<<1024, 256>>>(wo, wh + WOFF_O, wl + WOFF_O, 262144);
    split_kernel<<<4096, 256>>>(w1, wh + WOFF_1, wl + WOFF_1, 1048576);
    split_kernel<<<4096, 256>>>(w2, wh + WOFF_2, wl + WOFF_2, 1048576);

    // LN1 -> bf16 hi/lo activations
    ln_partial<<<gRed, 256>>>(x);
    ln_finalize<<<BB, 256>>>();
    ln_apply_split<<<4096, 256>>>(x, ah, al);
    // QKV projections -> split bf16 outputs directly
    mm_gemm<<<gProj, 256, MMG_SMEM>>>(ah, al, wh + WOFF_Q, wl + WOFF_Q, bq, nullptr,
                                      nullptr, qh, ql, MTOT, DD, DD, 0);
    mm_gemm<<<gProj, 256, MMG_SMEM>>>(ah, al, wh + WOFF_K, wl + WOFF_K, bk, nullptr,
                                      nullptr, kh, kl, MTOT, DD, DD, 0);
    mm_gemm<<<gProj, 256, MMG_SMEM>>>(ah, al, wh + WOFF_V, wl + WOFF_V, bv, nullptr,
                                      nullptr, vh, vl, MTOT, DD, DD, 0);
    // tensor-core flash attention -> split bf16 o
    attn_tc<<<gAtt, 256, ATT_SMEM>>>(qh, ql, kh, kl, vh, vl, oh, ol);
    // output projection + residual(x) -> h (fp32)
    mm_gemm<<<gProj, 256, MMG_SMEM>>>(oh, ol, wh + WOFF_O, wl + WOFF_O, bo, x,
                                      h, nullptr, nullptr, MTOT, DD, DD, 0);
    // LN2 -> bf16 hi/lo
    ln_partial<<<gRed, 256>>>(h);
    ln_finalize<<<BB, 256>>>();
    ln_apply_split<<<4096, 256>>>(h, ah, al);
    // FFN1 (relu) -> split bf16 hidden
    mm_gemm<<<gFF1, 256, MMG_SMEM>>>(ah, al, wh + WOFF_1, wl + WOFF_1, b1, nullptr,
                                     nullptr, fh, fl, MTOT, FFD, DD, 1);
    // FFN2 + residual(x) -> out (fp32)
    mm_gemm<<<gProj, 256, MMG_SMEM>>>(fh, fl, wh + WOFF_2, wl + WOFF_2, b2, x,
                                      out, nullptr, nullptr, MTOT, DD, FFD, 0);
}

// round 12
// speedup vs baseline: 2.2478x; 1.3344x over previous
#include <cuda_runtime.h>
#include <cuda_fp16.h>
#include <cstdint>
#include <math.h>

#define BB  2
#define LL  2048
#define DD  1024
#define HH  16
#define DHD 64
#define FFD 4096
#define MTOT (BB*LL)          // 4096 rows

// ---------------- scratch (static device globals; no allocation) -------------
__device__ float g_h [(size_t)MTOT*DD];    // pre-LN2 tensor (o@wo+bo+x)
__device__ float g_psum[BB*1024];
__device__ float g_psq [BB*1024];
__device__ float g_mu  [BB];
__device__ float g_rstd[BB];

// fp16 buffers (activations single, K/V split hi/lo)
__device__ __half g_a [(size_t)MTOT*DD];     // LN output (single fp16)
__device__ __half g_f [(size_t)MTOT*FFD];    // FFN hidden (single fp16)
__device__ __half g_qh[(size_t)MTOT*DD];
__device__ __half g_kh[(size_t)MTOT*DD];
__device__ __half g_kl[(size_t)MTOT*DD];
__device__ __half g_vh[(size_t)MTOT*DD];
__device__ __half g_vl[(size_t)MTOT*DD];
__device__ __half g_o [(size_t)MTOT*DD];     // attention output (single fp16)
// fp16 hi/lo weights: wq@0, wk@1M, wv@2M, wo@3M, w1@4M(4M), w2@8M(4M)
#define WOFF_Q  ((size_t)0)
#define WOFF_K  ((size_t)1024*1024)
#define WOFF_V  ((size_t)2*1024*1024)
#define WOFF_O  ((size_t)3*1024*1024)
#define WOFF_1  ((size_t)4*1024*1024)
#define WOFF_2  ((size_t)8*1024*1024)
__device__ __half g_wh[(size_t)12*1024*1024];
__device__ __half g_wl[(size_t)12*1024*1024];

// ======================= PTX helpers (baseline ISA, no 'a' features) =========
__device__ __forceinline__ uint32_t smem_u32(const void* p) {
    uint32_t a;
    asm("{ .reg .u64 t; cvta.to.shared.u64 t, %1; cvt.u32.u64 %0, t; }" : "=r"(a) : "l"(p));
    return a;
}
#define SWZ128(o) ((o) ^ (((o) >> 3) & 0x70))

#define CP_ASYNC16(dst, src) \
    asm volatile("cp.async.cg.shared.global [%0], [%1], 16;" :: "r"(dst), "l"(src))
#define CP_COMMIT() asm volatile("cp.async.commit_group;" ::: "memory")
#define CP_WAIT(n)  asm volatile("cp.async.wait_group %0;" :: "n"(n) : "memory")

__device__ __forceinline__ void ldsm_x4(uint32_t* r, uint32_t addr) {
    asm volatile("ldmatrix.sync.aligned.m8n8.x4.shared.b16 {%0,%1,%2,%3}, [%4];"
        : "=r"(r[0]), "=r"(r[1]), "=r"(r[2]), "=r"(r[3]) : "r"(addr));
}
__device__ __forceinline__ void ldsm_x4_t(uint32_t* r, uint32_t addr) {
    asm volatile("ldmatrix.sync.aligned.m8n8.x4.trans.shared.b16 {%0,%1,%2,%3}, [%4];"
        : "=r"(r[0]), "=r"(r[1]), "=r"(r[2]), "=r"(r[3]) : "r"(addr));
}
__device__ __forceinline__ void mma16816(float* c, const uint32_t* a, const uint32_t* b) {
    asm volatile(
        "mma.sync.aligned.m16n8k16.row.col.f32.f16.f16.f32 "
        "{%0,%1,%2,%3}, {%4,%5,%6,%7}, {%8,%9}, {%0,%1,%2,%3};"
        : "+f"(c[0]), "+f"(c[1]), "+f"(c[2]), "+f"(c[3])
        : "r"(a[0]), "r"(a[1]), "r"(a[2]), "r"(a[3]), "r"(b[0]), "r"(b[1]));
}
// pack two fp32 -> half2 bits (lo = p0, hi = p1)
__device__ __forceinline__ uint32_t pack_hf2(float p0, float p1) {
    __half2 h = __floats2half2_rn(p0, p1);
    return *(uint32_t*)&h;
}

// ---------------- LayerNorm over (L,D) jointly per batch ---------------------
__global__ void ln_partial(const float* __restrict__ x) {
    int b = blockIdx.y, blk = blockIdx.x;
    const float4* xb = (const float4*)x + (size_t)b*(LL*DD/4) + (size_t)blk*512;
    float s = 0.f, sq = 0.f;
    for (int i = threadIdx.x; i < 512; i += 256) {
        float4 v = xb[i];
        s  += v.x + v.y + v.z + v.w;
        sq += v.x*v.x + v.y*v.y + v.z*v.z + v.w*v.w;
    }
    __shared__ float ss[256], ssq[256];
    ss[threadIdx.x] = s; ssq[threadIdx.x] = sq;
    __syncthreads();
    for (int st = 128; st > 0; st >>= 1) {
        if (threadIdx.x < st) { ss[threadIdx.x] += ss[threadIdx.x+st]; ssq[threadIdx.x] += ssq[threadIdx.x+st]; }
        __syncthreads();
    }
    if (threadIdx.x == 0) { g_psum[b*1024+blk] = ss[0]; g_psq[b*1024+blk] = ssq[0]; }
}

__global__ void ln_finalize() {
    int b = blockIdx.x, tid = threadIdx.x;
    float s = 0.f, sq = 0.f;
    for (int i = tid; i < 1024; i += 256) { s += g_psum[b*1024+i]; sq += g_psq[b*1024+i]; }
    __shared__ float ss[256], ssq[256];
    ss[tid] = s; ssq[tid] = sq;
    __syncthreads();
    for (int st = 128; st > 0; st >>= 1) {
        if (tid < st) { ss[tid] += ss[tid+st]; ssq[tid] += ssq[tid+st]; }
        __syncthreads();
    }
    if (tid == 0) {
        float n   = (float)LL * (float)DD;
        float mu  = ss[0] / n;
        float var = ssq[0] / n - mu*mu;
        g_mu[b]   = mu;
        g_rstd[b] = rsqrtf(var + 1e-5f);
    }
}

// normalize -> single fp16
__global__ void ln_apply_f16(const float* __restrict__ in, __half* __restrict__ out) {
    int i = blockIdx.x*256 + threadIdx.x;           // float4 index
    int b = (i >= (LL*DD/4)) ? 1 : 0;
    float mu = g_mu[b], r = g_rstd[b];
    float4 v = ((const float4*)in)[i];
    uint2 p;
    p.x = pack_hf2((v.x-mu)*r, (v.y-mu)*r);
    p.y = pack_hf2((v.z-mu)*r, (v.w-mu)*r);
    ((uint2*)out)[i] = p;
}

// split fp32 -> fp16 hi/lo (weights)
__global__ void split_kernel(const float* __restrict__ in,
                             __half* __restrict__ hi, __half* __restrict__ lo, int n4) {
    int i = blockIdx.x*256 + threadIdx.x;
    if (i >= n4) return;
    float4 v = ((const float4*)in)[i];
    __half h0 = __float2half(v.x), h1 = __float2half(v.y);
    __half h2 = __float2half(v.z), h3 = __float2half(v.w);
    float l0 = v.x - __half2float(h0), l1 = v.y - __half2float(h1);
    float l2 = v.z - __half2float(h2), l3 = v.w - __half2float(h3);
    uint2 ph, pl;
    ph.x = ((uint32_t)__half_as_ushort(h1) << 16) | (uint32_t)__half_as_ushort(h0);
    ph.y = ((uint32_t)__half_as_ushort(h3) << 16) | (uint32_t)__half_as_ushort(h2);
    pl.x = pack_hf2(l0, l1);
    pl.y = pack_hf2(l2, l3);
    ((uint2*)hi)[i] = ph;
    ((uint2*)lo)[i] = pl;
}

// =============== mma.sync GEMM: C[m,n] = sum_k A[m,k]*W[n,k] (+bias,resid,relu)
// CTA tile 128x128, K-chunk 64 fp16, 3-stage cp.async pipeline.
// A single fp16; W split hi/lo -> 2 MMA passes: A*Wh + A*Wl.
// Output: fp32 C, or fp16 Chi (and optional Clo residual split for K/V).
#define STAGES 3
#define TILEB 16384                 // one 128x64 fp16 tile (128B rows)
#define STAGE_BYTES (3*TILEB)       // A, Bh, Bl
#define MMG_SMEM (STAGES*STAGE_BYTES + 1024)

__device__ __forceinline__ void issue_chunk(
    uint32_t sslot,
    const __half* a0, const __half* b0, const __half* b1,
    int K, int k0, int tid)
{
    #pragma unroll
    for (int it = 0; it < 4; it++) {
        int idx = it*256 + tid;
        int row = idx >> 3, s = idx & 7;
        uint32_t off = SWZ128((uint32_t)(row*128 + s*16));
        size_t go = (size_t)row*K + k0 + s*8;
        CP_ASYNC16(sslot + off,            a0 + go);
        CP_ASYNC16(sslot + TILEB + off,    b0 + go);
        CP_ASYNC16(sslot + 2*TILEB + off,  b1 + go);
    }
}

__global__ __launch_bounds__(256) void mm_gemm(
    const __half* __restrict__ A,
    const __half* __restrict__ Bh, const __half* __restrict__ Bl,
    const float* __restrict__ bias, const float* __restrict__ resid,
    float* __restrict__ C, __half* __restrict__ Chi, __half* __restrict__ Clo,
    int M, int N, int K, int relu)
{
    extern __shared__ char smraw[];
    char* smb = (char*)(((uintptr_t)smraw + 1023) & ~(uintptr_t)1023);
    uint32_t sbase = smem_u32(smb);

    const int tid  = threadIdx.x;
    const int warp = tid >> 5, lane = tid & 31;
    const int m0 = blockIdx.y * 128, n0 = blockIdx.x * 128;
    const int wm = (warp >> 1) * 32;
    const int wn = (warp & 1) * 64;

    const __half* tA  = A  + (size_t)m0 * K;
    const __half* tB0 = Bh + (size_t)n0 * K;
    const __half* tB1 = Bl + (size_t)n0 * K;

    float acc[2][8][4];
    #pragma unroll
    for (int i = 0; i < 2; i++)
        #pragma unroll
        for (int j = 0; j < 8; j++)
            #pragma unroll
            for (int q = 0; q < 4; q++) acc[i][j][q] = 0.f;

    const int nch = K >> 6;
    issue_chunk(sbase + 0*STAGE_BYTES, tA, tB0, tB1, K, 0, tid);
    CP_COMMIT();
    issue_chunk(sbase + 1*STAGE_BYTES, tA, tB0, tB1, K, 64, tid);
    CP_COMMIT();

    const int arow  = (lane & 7) + ((lane >> 3) & 1) * 8;
    const int akoff = (lane >> 4) * 16;
    const int brow  = (lane & 7) + (lane >> 4) * 8;
    const int bkoff = ((lane >> 3) & 1) * 16;

    for (int c = 0; c < nch; c++) {
        CP_WAIT(1);
        __syncthreads();
        int cn = c + STAGES - 1;
        if (cn < nch)
            issue_chunk(sbase + (cn % STAGES)*STAGE_BYTES, tA, tB0, tB1, K, cn*64, tid);
        CP_COMMIT();

        uint32_t sl = sbase + (c % STAGES)*STAGE_BYTES;
        #pragma unroll
        for (int ks = 0; ks < 4; ks++) {
            uint32_t ah[2][4];
            #pragma unroll
            for (int mf = 0; mf < 2; mf++) {
                uint32_t off = SWZ128((uint32_t)((wm + mf*16 + arow)*128 + ks*32 + akoff));
                ldsm_x4(ah[mf], sl + off);
            }
            #pragma unroll
            for (int g = 0; g < 4; g++) {
                uint32_t bh[4], bl[4];
                uint32_t off = SWZ128((uint32_t)((wn + g*16 + brow)*128 + ks*32 + bkoff));
                ldsm_x4(bh, sl + TILEB + off);
                ldsm_x4(bl, sl + 2*TILEB + off);
                #pragma unroll
                for (int mf = 0; mf < 2; mf++) {
                    mma16816(acc[mf][2*g],   ah[mf], bh);
                    mma16816(acc[mf][2*g],   ah[mf], bl);
                    mma16816(acc[mf][2*g+1], ah[mf], bh + 2);
                    mma16816(acc[mf][2*g+1], ah[mf], bl + 2);
                }
            }
        }
    }

    // epilogue
    const int rbase = m0 + wm + (lane >> 2);
    const int cbase = n0 + wn + (lane & 3) * 2;
    #pragma unroll
    for (int nf = 0; nf < 8; nf++) {
        const int col = cbase + nf*8;
        float2 bv = *(const float2*)(bias + col);
        #pragma unroll
        for (int mf = 0; mf < 2; mf++) {
            int r0 = rbase + mf*16;
            #pragma unroll
            for (int half_ = 0; half_ < 2; half_++) {
                int rr = r0 + half_*8;
                float vx = acc[mf][nf][half_*2+0] + bv.x;
                float vy = acc[mf][nf][half_*2+1] + bv.y;
                if (resid) {
                    float2 rv = *(const float2*)(resid + (size_t)rr*N + col);
                    vx += rv.x; vy += rv.y;
                }
                if (relu) { vx = fmaxf(vx, 0.f); vy = fmaxf(vy, 0.f); }
                if (Chi) {
                    __half hx = __float2half(vx), hy = __float2half(vy);
                    uint32_t ph = ((uint32_t)__half_as_ushort(hy) << 16) | (uint32_t)__half_as_ushort(hx);
                    *(uint32_t*)(Chi + (size_t)rr*N + col) = ph;
                    if (Clo) {
                        float lx = vx - __half2float(hx), ly = vy - __half2float(hy);
                        *(uint32_t*)(Clo + (size_t)rr*N + col) = pack_hf2(lx, ly);
                    }
                } else {
                    float2 v2 = make_float2(vx, vy);
                    *(float2*)(C + (size_t)rr*N + col) = v2;
                }
            }
        }
    }
}

// ======= tensor-core flash attention: O = softmax(Q K^T * 0.25) V ============
// CTA: 128 q-rows of one (b,h). 8 warps x 16 rows. Key tiles of 64.
// S = Q*Kh + Q*Kl (2-pass), PV = P*Vh + P*Vl (2-pass), fp32 softmax, P fp16.
// smem: Q 16KB + 2 stages x (kh,kl,vh,vl) 32KB = 80KB.
#define ATT_Q_BYTES 16384
#define ATT_KV_STAGE 32768
#define ATT_SMEM (ATT_Q_BYTES + 2*ATT_KV_STAGE)

__device__ __forceinline__ void attn_issue_kv(
    uint32_t kvs,
    const __half* kh, const __half* kl,
    const __half* vh, const __half* vl,
    size_t gbase, int tid)
{
    #pragma unroll
    for (int t = 0; t < 2; t++) {
        int idx = t*256 + tid;
        int row = idx >> 3, seg = idx & 7;
        uint32_t off = SWZ128((uint32_t)(row*128 + seg*16));
        size_t go = gbase + (size_t)row*DD + seg*8;
        CP_ASYNC16(kvs + off,          kh + go);
        CP_ASYNC16(kvs + 8192 + off,   kl + go);
        CP_ASYNC16(kvs + 16384 + off,  vh + go);
        CP_ASYNC16(kvs + 24576 + off,  vl + go);
    }
}

__global__ __launch_bounds__(256) void attn_tc(
    const __half* __restrict__ q,
    const __half* __restrict__ kh, const __half* __restrict__ kl,
    const __half* __restrict__ vh, const __half* __restrict__ vl,
    __half* __restrict__ o)
{
    extern __shared__ char smraw[];
    uint32_t sb = smem_u32(smraw);
    const int tid = threadIdx.x, warp = tid >> 5, lane = tid & 31;
    const int qt = blockIdx.x;
    const int b = blockIdx.y >> 4, h = blockIdx.y & 15;
    const int wm = warp * 16;

    const size_t qbase  = ((size_t)(b*LL + qt*128))*DD + (size_t)h*DHD;
    const size_t kvbase = ((size_t)(b*LL))*DD + (size_t)h*DHD;

    // prologue: Q + KV tile 0 -> one group
    #pragma unroll
    for (int t = 0; t < 4; t++) {
        int idx = t*256 + tid;
        int row = idx >> 3, seg = idx & 7;
        uint32_t off = SWZ128((uint32_t)(row*128 + seg*16));
        size_t go = qbase + (size_t)row*DD + seg*8;
        CP_ASYNC16(sb + off, q + go);
    }
    attn_issue_kv(sb + ATT_Q_BYTES, kh, kl, vh, vl, kvbase, tid);
    CP_COMMIT();

    float sO[8][4];
    #pragma unroll
    for (int j = 0; j < 8; j++)
        #pragma unroll
        for (int qq = 0; qq < 4; qq++) sO[j][qq] = 0.f;
    float mrow[2] = {-1e30f, -1e30f};
    float lrow[2] = {0.f, 0.f};

    const int arow  = (lane & 7) + ((lane >> 3) & 1) * 8;
    const int akoff = (lane >> 4) * 16;
    const int brow  = (lane & 7) + (lane >> 4) * 8;
    const int bkoff = ((lane >> 3) & 1) * 16;
    const int vgrp  = lane >> 3, vr = lane & 7;   // trans-ldsm addressing

    const int NT = LL / 64;   // 32 key tiles
    for (int kt = 0; kt < NT; kt++) {
        __syncthreads();
        if (kt + 1 < NT) {
            attn_issue_kv(sb + ATT_Q_BYTES + ((kt+1)&1)*ATT_KV_STAGE,
                          kh, kl, vh, vl, kvbase + (size_t)(kt+1)*64*DD, tid);
            CP_COMMIT();
            CP_WAIT(1);
        } else {
            CP_WAIT(0);
        }
        __syncthreads();

        uint32_t kvs = sb + ATT_Q_BYTES + (kt&1)*ATT_KV_STAGE;

        // ---- S = Q K^T (2-pass: Kh + Kl) ----
        float sS[8][4];
        #pragma unroll
        for (int j = 0; j < 8; j++)
            #pragma unroll
            for (int qq = 0; qq < 4; qq++) sS[j][qq] = 0.f;

        #pragma unroll
        for (int ks = 0; ks < 4; ks++) {
            uint32_t aq[4];
            uint32_t offa = SWZ128((uint32_t)((wm + arow)*128 + ks*32 + akoff));
            ldsm_x4(aq, sb + offa);
            #pragma unroll
            for (int g = 0; g < 4; g++) {
                uint32_t bh_[4], bl_[4];
                uint32_t offb = SWZ128((uint32_t)((g*16 + brow)*128 + ks*32 + bkoff));
                ldsm_x4(bh_, kvs + offb);
                ldsm_x4(bl_, kvs + 8192 + offb);
                mma16816(sS[2*g],   aq, bh_);
                mma16816(sS[2*g],   aq, bl_);
                mma16816(sS[2*g+1], aq, bh_ + 2);
                mma16816(sS[2*g+1], aq, bl_ + 2);
            }
        }

        // scale (faithful source bug: 1/sqrt(H) = 0.25)
        #pragma unroll
        for (int j = 0; j < 8; j++)
            #pragma unroll
            for (int qq = 0; qq < 4; qq++) sS[j][qq] *= 0.25f;

        // ---- online softmax (rows: rr=0 -> lane>>2, rr=1 -> +8) ----
        #pragma unroll
        for (int rr = 0; rr < 2; rr++) {
            float tm = -1e30f;
            #pragma unroll
            for (int j = 0; j < 8; j++) {
                tm = fmaxf(tm, sS[j][rr*2+0]);
                tm = fmaxf(tm, sS[j][rr*2+1]);
            }
            tm = fmaxf(tm, __shfl_xor_sync(0xffffffffu, tm, 1));
            tm = fmaxf(tm, __shfl_xor_sync(0xffffffffu, tm, 2));
            float mnew = fmaxf(mrow[rr], tm);
            float corr = __expf(mrow[rr] - mnew);
            mrow[rr] = mnew;
            float psum = 0.f;
            #pragma unroll
            for (int j = 0; j < 8; j++) {
                float p0 = __expf(sS[j][rr*2+0] - mnew);
                float p1 = __expf(sS[j][rr*2+1] - mnew);
                sS[j][rr*2+0] = p0; sS[j][rr*2+1] = p1;
                psum += p0 + p1;
            }
            psum += __shfl_xor_sync(0xffffffffu, psum, 1);
            psum += __shfl_xor_sync(0xffffffffu, psum, 2);
            lrow[rr] = lrow[rr]*corr + psum;
            #pragma unroll
            for (int j = 0; j < 8; j++) {
                sO[j][rr*2+0] *= corr;
                sO[j][rr*2+1] *= corr;
            }
        }

        // ---- pack P (A-fragments for PV, fp16) ----
        uint32_t pa[4][4];
        #pragma unroll
        for (int k = 0; k < 4; k++) {
            pa[k][0] = pack_hf2(sS[2*k][0],   sS[2*k][1]);
            pa[k][1] = pack_hf2(sS[2*k][2],   sS[2*k][3]);
            pa[k][2] = pack_hf2(sS[2*k+1][0], sS[2*k+1][1]);
            pa[k][3] = pack_hf2(sS[2*k+1][2], sS[2*k+1][3]);
        }

        // ---- O += P V (2-pass: Vh + Vl) ----
        #pragma unroll
        for (int ks = 0; ks < 4; ks++) {
            #pragma unroll
            for (int g = 0; g < 4; g++) {
                uint32_t bvh[4], bvl[4];
                int row = ks*16 + (vgrp & 1)*8 + vr;
                int colb = (g*16 + (vgrp >> 1)*8) * 2;
                uint32_t offv = SWZ128((uint32_t)(row*128 + colb));
                ldsm_x4_t(bvh, kvs + 16384 + offv);
                ldsm_x4_t(bvl, kvs + 24576 + offv);
                mma16816(sO[2*g],   pa[ks], bvh);
                mma16816(sO[2*g],   pa[ks], bvl);
                mma16816(sO[2*g+1], pa[ks], bvh + 2);
                mma16816(sO[2*g+1], pa[ks], bvl + 2);
            }
        }
    }

    // ---- epilogue: normalize + fp16 store ----
    #pragma unroll
    for (int rr = 0; rr < 2; rr++) {
        float inv = 1.0f / lrow[rr];
        int row = qt*128 + wm + rr*8 + (lane >> 2);
        size_t ob = ((size_t)(b*LL + row))*DD + (size_t)h*DHD + (lane & 3)*2;
        #pragma unroll
        for (int j = 0; j < 8; j++) {
            float v0 = sO[j][rr*2+0] * inv;
            float v1 = sO[j][rr*2+1] * inv;
            *(uint32_t*)(o + ob + j*8) = pack_hf2(v0, v1);
        }
    }
}

// ---------------- launcher ---------------------------------------------------
extern "C" void kernel_launch(void* const* d_in, const int* in_sizes, int n_in,
                              void* d_out, int out_size) {
    const float* x  = (const float*)d_in[0];
    const float* wq = (const float*)d_in[1];
    const float* bq = (const float*)d_in[2];
    const float* wk = (const float*)d_in[3];
    const float* bk = (const float*)d_in[4];
    const float* wv = (const float*)d_in[5];
    const float* bv = (const float*)d_in[6];
    const float* wo = (const float*)d_in[7];
    const float* bo = (const float*)d_in[8];
    const float* w1 = (const float*)d_in[9];
    const float* b1 = (const float*)d_in[10];
    const float* w2 = (const float*)d_in[11];
    const float* b2 = (const float*)d_in[12];
    float* out = (float*)d_out;

    cudaFuncSetAttribute((const void*)mm_gemm,
                         cudaFuncAttributeMaxDynamicSharedMemorySize, MMG_SMEM);
    cudaFuncSetAttribute((const void*)attn_tc,
                         cudaFuncAttributeMaxDynamicSharedMemorySize, ATT_SMEM);

    void *ph_, *pa, *pf, *pwh, *pwl;
    void *pqh, *pkh, *pkl, *pvh, *pvl, *po;
    cudaGetSymbolAddress(&ph_, g_h);
    cudaGetSymbolAddress(&pa,  g_a);
    cudaGetSymbolAddress(&pf,  g_f);
    cudaGetSymbolAddress(&pwh, g_wh);
    cudaGetSymbolAddress(&pwl, g_wl);
    cudaGetSymbolAddress(&pqh, g_qh);
    cudaGetSymbolAddress(&pkh, g_kh);
    cudaGetSymbolAddress(&pkl, g_kl);
    cudaGetSymbolAddress(&pvh, g_vh);
    cudaGetSymbolAddress(&pvl, g_vl);
    cudaGetSymbolAddress(&po,  g_o);
    float* h = (float*)ph_;
    __half* a  = (__half*)pa;
    __half* f  = (__half*)pf;
    __half* wh = (__half*)pwh;
    __half* wl = (__half*)pwl;
    __half* qh = (__half*)pqh;
    __half* kh = (__half*)pkh;
    __half* kl = (__half*)pkl;
    __half* vh = (__half*)pvh;
    __half* vl = (__half*)pvl;
    __half* o  = (__half*)po;

    dim3 gRed(1024, BB);
    dim3 gProj(DD/128,  MTOT/128);   // (8, 32)
    dim3 gFF1 (FFD/128, MTOT/128);   // (32, 32)
    dim3 gAtt (LL/128, BB*HH);       // (16, 32)

    // weight splits (hi/lo fp16), every launch — deterministic
    split_kernel<<<1024, 256>>>(wq, wh + WOFF_Q, wl + WOFF_Q, 262144);
    split_kernel<<<1024, 256>>>(wk, wh + WOFF_K, wl + WOFF_K, 262144);
    split_kernel<<<1024, 256>>>(wv, wh + WOFF_V, wl + WOFF_V, 262144);
    split_kernel<<<1024, 256>>>(wo, wh + WOFF_O, wl + WOFF_O, 262144);
    split_kernel<<<4096, 256>>>(w1, wh + WOFF_1, wl + WOFF_1, 1048576);
    split_kernel<<<4096, 256>>>(w2, wh + WOFF_2, wl + WOFF_2, 1048576);

    // LN1 -> fp16 activations
    ln_partial<<<gRed, 256>>>(x);
    ln_finalize<<<BB, 256>>>();
    ln_apply_f16<<<4096, 256>>>(x, a);
    // QKV projections (Q single; K,V hi/lo split outputs)
    mm_gemm<<<gProj, 256, MMG_SMEM>>>(a, wh + WOFF_Q, wl + WOFF_Q, bq, nullptr,
                                      nullptr, qh, nullptr, MTOT, DD, DD, 0);
    mm_gemm<<<gProj, 256, MMG_SMEM>>>(a, wh + WOFF_K, wl + WOFF_K, bk, nullptr,
                                      nullptr, kh, kl, MTOT, DD, DD, 0);
    mm_gemm<<<gProj, 256, MMG_SMEM>>>(a, wh + WOFF_V, wl + WOFF_V, bv, nullptr,
                                      nullptr, vh, vl, MTOT, DD, DD, 0);
    // tensor-core flash attention -> fp16 o
    attn_tc<<<gAtt, 256, ATT_SMEM>>>(qh, kh, kl, vh, vl, o);
    // output projection + residual(x) -> h (fp32)
    mm_gemm<<<gProj, 256, MMG_SMEM>>>(o, wh + WOFF_O, wl + WOFF_O, bo, x,
                                      h, nullptr, nullptr, MTOT, DD, DD, 0);
    // LN2 -> fp16
    ln_partial<<<gRed, 256>>>(h);
    ln_finalize<<<BB, 256>>>();
    ln_apply_f16<<<4096, 256>>>(h, a);
    // FFN1 (relu) -> fp16 hidden
    mm_gemm<<<gFF1, 256, MMG_SMEM>>>(a, wh + WOFF_1, wl + WOFF_1, b1, nullptr,
                                     nullptr, f, nullptr, MTOT, FFD, DD, 1);
    // FFN2 + residual(x) -> out (fp32)
    mm_gemm<<<gProj, 256, MMG_SMEM>>>(f, wh + WOFF_2, wl + WOFF_2, b2, x,
                                      out, nullptr, nullptr, MTOT, DD, FFD, 0);
}

// round 14
// speedup vs baseline: 2.8460x; 1.2661x over previous
#include <cuda_runtime.h>
#include <cuda_fp16.h>
#include <cstdint>
#include <math.h>

#define BB  2
#define LL  2048
#define DD  1024
#define HH  16
#define DHD 64
#define FFD 4096
#define MTOT (BB*LL)          // 4096 rows

// ---------------- scratch (static device globals; no allocation) -------------
__device__ float g_h [(size_t)MTOT*DD];    // pre-LN2 tensor (o@wo+bo+x)
__device__ float g_psum[BB*1024];
__device__ float g_psq [BB*1024];
__device__ float g_mu  [BB];
__device__ float g_rstd[BB];

// fp16 buffers (activations single, K/V split hi/lo)
__device__ __half g_a [(size_t)MTOT*DD];     // LN output (single fp16)
__device__ __half g_f [(size_t)MTOT*FFD];    // FFN hidden (single fp16)
__device__ __half g_qh[(size_t)MTOT*DD];
__device__ __half g_kh[(size_t)MTOT*DD];
__device__ __half g_kl[(size_t)MTOT*DD];
__device__ __half g_vh[(size_t)MTOT*DD];
__device__ __half g_vl[(size_t)MTOT*DD];
__device__ __half g_o [(size_t)MTOT*DD];     // attention output (single fp16)
// fp16 weights: hi for all, lo only for q/k/v/o (ffn weights single-pass)
#define WOFF_Q  ((size_t)0)
#define WOFF_K  ((size_t)1024*1024)
#define WOFF_V  ((size_t)2*1024*1024)
#define WOFF_O  ((size_t)3*1024*1024)
#define WOFF_1  ((size_t)4*1024*1024)
#define WOFF_2  ((size_t)8*1024*1024)
__device__ __half g_wh[(size_t)12*1024*1024];
__device__ __half g_wl[(size_t)4*1024*1024];

// ======================= PTX helpers (baseline ISA, no 'a' features) =========
__device__ __forceinline__ uint32_t smem_u32(const void* p) {
    uint32_t a;
    asm("{ .reg .u64 t; cvta.to.shared.u64 t, %1; cvt.u32.u64 %0, t; }" : "=r"(a) : "l"(p));
    return a;
}
#define SWZ128(o) ((o) ^ (((o) >> 3) & 0x70))

#define CP_ASYNC16(dst, src) \
    asm volatile("cp.async.cg.shared.global [%0], [%1], 16;" :: "r"(dst), "l"(src))
#define CP_COMMIT() asm volatile("cp.async.commit_group;" ::: "memory")
#define CP_WAIT(n)  asm volatile("cp.async.wait_group %0;" :: "n"(n) : "memory")

__device__ __forceinline__ void ldsm_x4(uint32_t* r, uint32_t addr) {
    asm volatile("ldmatrix.sync.aligned.m8n8.x4.shared.b16 {%0,%1,%2,%3}, [%4];"
        : "=r"(r[0]), "=r"(r[1]), "=r"(r[2]), "=r"(r[3]) : "r"(addr));
}
__device__ __forceinline__ void ldsm_x4_t(uint32_t* r, uint32_t addr) {
    asm volatile("ldmatrix.sync.aligned.m8n8.x4.trans.shared.b16 {%0,%1,%2,%3}, [%4];"
        : "=r"(r[0]), "=r"(r[1]), "=r"(r[2]), "=r"(r[3]) : "r"(addr));
}
__device__ __forceinline__ void mma16816(float* c, const uint32_t* a, const uint32_t* b) {
    asm volatile(
        "mma.sync.aligned.m16n8k16.row.col.f32.f16.f16.f32 "
        "{%0,%1,%2,%3}, {%4,%5,%6,%7}, {%8,%9}, {%0,%1,%2,%3};"
        : "+f"(c[0]), "+f"(c[1]), "+f"(c[2]), "+f"(c[3])
        : "r"(a[0]), "r"(a[1]), "r"(a[2]), "r"(a[3]), "r"(b[0]), "r"(b[1]));
}
// pack two fp32 -> half2 bits (lo = p0, hi = p1)
__device__ __forceinline__ uint32_t pack_hf2(float p0, float p1) {
    __half2 h = __floats2half2_rn(p0, p1);
    return *(uint32_t*)&h;
}

// ---------------- LayerNorm over (L,D) jointly per batch ---------------------
__global__ void ln_partial(const float* __restrict__ x) {
    int b = blockIdx.y, blk = blockIdx.x;
    const float4* xb = (const float4*)x + (size_t)b*(LL*DD/4) + (size_t)blk*512;
    float s = 0.f, sq = 0.f;
    for (int i = threadIdx.x; i < 512; i += 256) {
        float4 v = xb[i];
        s  += v.x + v.y + v.z + v.w;
        sq += v.x*v.x + v.y*v.y + v.z*v.z + v.w*v.w;
    }
    __shared__ float ss[256], ssq[256];
    ss[threadIdx.x] = s; ssq[threadIdx.x] = sq;
    __syncthreads();
    for (int st = 128; st > 0; st >>= 1) {
        if (threadIdx.x < st) { ss[threadIdx.x] += ss[threadIdx.x+st]; ssq[threadIdx.x] += ssq[threadIdx.x+st]; }
        __syncthreads();
    }
    if (threadIdx.x == 0) { g_psum[b*1024+blk] = ss[0]; g_psq[b*1024+blk] = ssq[0]; }
}

__global__ void ln_finalize() {
    int b = blockIdx.x, tid = threadIdx.x;
    float s = 0.f, sq = 0.f;
    for (int i = tid; i < 1024; i += 256) { s += g_psum[b*1024+i]; sq += g_psq[b*1024+i]; }
    __shared__ float ss[256], ssq[256];
    ss[tid] = s; ssq[tid] = sq;
    __syncthreads();
    for (int st = 128; st > 0; st >>= 1) {
        if (tid < st) { ss[tid] += ss[tid+st]; ssq[tid] += ssq[tid+st]; }
        __syncthreads();
    }
    if (tid == 0) {
        float n   = (float)LL * (float)DD;
        float mu  = ss[0] / n;
        float var = ssq[0] / n - mu*mu;
        g_mu[b]   = mu;
        g_rstd[b] = rsqrtf(var + 1e-5f);
    }
}

// normalize -> single fp16
__global__ void ln_apply_f16(const float* __restrict__ in, __half* __restrict__ out) {
    int i = blockIdx.x*256 + threadIdx.x;           // float4 index
    int b = (i >= (LL*DD/4)) ? 1 : 0;
    float mu = g_mu[b], r = g_rstd[b];
    float4 v = ((const float4*)in)[i];
    uint2 p;
    p.x = pack_hf2((v.x-mu)*r, (v.y-mu)*r);
    p.y = pack_hf2((v.z-mu)*r, (v.w-mu)*r);
    ((uint2*)out)[i] = p;
}

// split fp32 -> fp16 hi/lo (q/k/v/o weights)
__global__ void split_kernel(const float* __restrict__ in,
                             __half* __restrict__ hi, __half* __restrict__ lo, int n4) {
    int i = blockIdx.x*256 + threadIdx.x;
    if (i >= n4) return;
    float4 v = ((const float4*)in)[i];
    __half h0 = __float2half(v.x), h1 = __float2half(v.y);
    __half h2 = __float2half(v.z), h3 = __float2half(v.w);
    float l0 = v.x - __half2float(h0), l1 = v.y - __half2float(h1);
    float l2 = v.z - __half2float(h2), l3 = v.w - __half2float(h3);
    uint2 ph, pl;
    ph.x = ((uint32_t)__half_as_ushort(h1) << 16) | (uint32_t)__half_as_ushort(h0);
    ph.y = ((uint32_t)__half_as_ushort(h3) << 16) | (uint32_t)__half_as_ushort(h2);
    pl.x = pack_hf2(l0, l1);
    pl.y = pack_hf2(l2, l3);
    ((uint2*)hi)[i] = ph;
    ((uint2*)lo)[i] = pl;
}

// cast fp32 -> fp16 (ffn weights, single precision pass)
__global__ void cast_kernel(const float* __restrict__ in, __half* __restrict__ out, int n4) {
    int i = blockIdx.x*256 + threadIdx.x;
    if (i >= n4) return;
    float4 v = ((const float4*)in)[i];
    uint2 p;
    p.x = pack_hf2(v.x, v.y);
    p.y = pack_hf2(v.z, v.w);
    ((uint2*)out)[i] = p;
}

// =============== mma.sync GEMM: C[m,n] = sum_k A[m,k]*W[n,k] (+bias,resid,relu)
// CTA tile 128x128, K-chunk 64 fp16, 2-stage cp.async double buffer, 2 CTA/SM.
// A single fp16; W hi (+optional lo -> 2 MMA passes).
// Output: fp32 C, or fp16 Chi (and optional Clo residual split for K/V).
#define TILEB 16384                 // one 128x64 fp16 tile (128B rows)
#define STAGE_BYTES (3*TILEB)       // A, Bh, Bl
#define MMG_SMEM (2*STAGE_BYTES + 1024)

__device__ __forceinline__ void issue_chunk(
    uint32_t sslot,
    const __half* a0, const __half* b0, const __half* b1,
    int K, int k0, int tid)
{
    #pragma unroll
    for (int it = 0; it < 4; it++) {
        int idx = it*256 + tid;
        int row = idx >> 3, s = idx & 7;
        uint32_t off = SWZ128((uint32_t)(row*128 + s*16));
        size_t go = (size_t)row*K + k0 + s*8;
        CP_ASYNC16(sslot + off,            a0 + go);
        CP_ASYNC16(sslot + TILEB + off,    b0 + go);
        if (b1) CP_ASYNC16(sslot + 2*TILEB + off, b1 + go);
    }
}

__global__ __launch_bounds__(256, 2) void mm_gemm(
    const __half* __restrict__ A,
    const __half* __restrict__ Bh, const __half* __restrict__ Bl,
    const float* __restrict__ bias, const float* __restrict__ resid,
    float* __restrict__ C, __half* __restrict__ Chi, __half* __restrict__ Clo,
    int M, int N, int K, int relu)
{
    extern __shared__ char smraw[];
    char* smb = (char*)(((uintptr_t)smraw + 1023) & ~(uintptr_t)1023);
    uint32_t sbase = smem_u32(smb);

    const int tid  = threadIdx.x;
    const int warp = tid >> 5, lane = tid & 31;
    const int m0 = blockIdx.y * 128, n0 = blockIdx.x * 128;
    const int wm = (warp >> 1) * 32;
    const int wn = (warp & 1) * 64;

    const __half* tA  = A  + (size_t)m0 * K;
    const __half* tB0 = Bh + (size_t)n0 * K;
    const __half* tB1 = Bl ? (Bl + (size_t)n0 * K) : (const __half*)nullptr;
    const bool twob = (Bl != nullptr);

    float acc[2][8][4];
    #pragma unroll
    for (int i = 0; i < 2; i++)
        #pragma unroll
        for (int j = 0; j < 8; j++)
            #pragma unroll
            for (int q = 0; q < 4; q++) acc[i][j][q] = 0.f;

    const int nch = K >> 6;
    issue_chunk(sbase, tA, tB0, tB1, K, 0, tid);
    CP_COMMIT();

    const int arow  = (lane & 7) + ((lane >> 3) & 1) * 8;
    const int akoff = (lane >> 4) * 16;
    const int brow  = (lane & 7) + (lane >> 4) * 8;
    const int bkoff = ((lane >> 3) & 1) * 16;

    for (int c = 0; c < nch; c++) {
        __syncthreads();            // all warps done reading the buffer we refill
        if (c + 1 < nch) {
            issue_chunk(sbase + ((c+1)&1)*STAGE_BYTES, tA, tB0, tB1, K, (c+1)*64, tid);
            CP_COMMIT();
            CP_WAIT(1);
        } else {
            CP_WAIT(0);
        }
        __syncthreads();

        uint32_t sl = sbase + (c & 1)*STAGE_BYTES;
        #pragma unroll
        for (int ks = 0; ks < 4; ks++) {
            uint32_t ah[2][4];
            #pragma unroll
            for (int mf = 0; mf < 2; mf++) {
                uint32_t off = SWZ128((uint32_t)((wm + mf*16 + arow)*128 + ks*32 + akoff));
                ldsm_x4(ah[mf], sl + off);
            }
            #pragma unroll
            for (int g = 0; g < 4; g++) {
                uint32_t bh[4];
                uint32_t off = SWZ128((uint32_t)((wn + g*16 + brow)*128 + ks*32 + bkoff));
                ldsm_x4(bh, sl + TILEB + off);
                if (twob) {
                    uint32_t bl[4];
                    ldsm_x4(bl, sl + 2*TILEB + off);
                    #pragma unroll
                    for (int mf = 0; mf < 2; mf++) {
                        mma16816(acc[mf][2*g],   ah[mf], bh);
                        mma16816(acc[mf][2*g],   ah[mf], bl);
                        mma16816(acc[mf][2*g+1], ah[mf], bh + 2);
                        mma16816(acc[mf][2*g+1], ah[mf], bl + 2);
                    }
                } else {
                    #pragma unroll
                    for (int mf = 0; mf < 2; mf++) {
                        mma16816(acc[mf][2*g],   ah[mf], bh);
                        mma16816(acc[mf][2*g+1], ah[mf], bh + 2);
                    }
                }
            }
        }
    }

    // epilogue
    const int rbase = m0 + wm + (lane >> 2);
    const int cbase = n0 + wn + (lane & 3) * 2;
    #pragma unroll
    for (int nf = 0; nf < 8; nf++) {
        const int col = cbase + nf*8;
        float2 bv = *(const float2*)(bias + col);
        #pragma unroll
        for (int mf = 0; mf < 2; mf++) {
            int r0 = rbase + mf*16;
            #pragma unroll
            for (int half_ = 0; half_ < 2; half_++) {
                int rr = r0 + half_*8;
                float vx = acc[mf][nf][half_*2+0] + bv.x;
                float vy = acc[mf][nf][half_*2+1] + bv.y;
                if (resid) {
                    float2 rv = *(const float2*)(resid + (size_t)rr*N + col);
                    vx += rv.x; vy += rv.y;
                }
                if (relu) { vx = fmaxf(vx, 0.f); vy = fmaxf(vy, 0.f); }
                if (Chi) {
                    __half hx = __float2half(vx), hy = __float2half(vy);
                    uint32_t ph = ((uint32_t)__half_as_ushort(hy) << 16) | (uint32_t)__half_as_ushort(hx);
                    *(uint32_t*)(Chi + (size_t)rr*N + col) = ph;
                    if (Clo) {
                        float lx = vx - __half2float(hx), ly = vy - __half2float(hy);
                        *(uint32_t*)(Clo + (size_t)rr*N + col) = pack_hf2(lx, ly);
                    }
                } else {
                    float2 v2 = make_float2(vx, vy);
                    *(float2*)(C + (size_t)rr*N + col) = v2;
                }
            }
        }
    }
}

// ======= tensor-core flash attention: O = softmax(Q K^T * 0.25) V ============
// CTA: 128 q-rows of one (b,h). 8 warps x 16 rows. Key tiles of 64.
// S = Q*Kh + Q*Kl (2-pass), PV = P*Vh + P*Vl (2-pass), fp32 softmax, P fp16.
// smem: Q 16KB + 2 stages x (kh,kl,vh,vl) 32KB = 80KB.
#define ATT_Q_BYTES 16384
#define ATT_KV_STAGE 32768
#define ATT_SMEM (ATT_Q_BYTES + 2*ATT_KV_STAGE)

__device__ __forceinline__ void attn_issue_kv(
    uint32_t kvs,
    const __half* kh, const __half* kl,
    const __half* vh, const __half* vl,
    size_t gbase, int tid)
{
    #pragma unroll
    for (int t = 0; t < 2; t++) {
        int idx = t*256 + tid;
        int row = idx >> 3, seg = idx & 7;
        uint32_t off = SWZ128((uint32_t)(row*128 + seg*16));
        size_t go = gbase + (size_t)row*DD + seg*8;
        CP_ASYNC16(kvs + off,          kh + go);
        CP_ASYNC16(kvs + 8192 + off,   kl + go);
        CP_ASYNC16(kvs + 16384 + off,  vh + go);
        CP_ASYNC16(kvs + 24576 + off,  vl + go);
    }
}

__global__ __launch_bounds__(256) void attn_tc(
    const __half* __restrict__ q,
    const __half* __restrict__ kh, const __half* __restrict__ kl,
    const __half* __restrict__ vh, const __half* __restrict__ vl,
    __half* __restrict__ o)
{
    extern __shared__ char smraw[];
    uint32_t sb = smem_u32(smraw);
    const int tid = threadIdx.x, warp = tid >> 5, lane = tid & 31;
    const int qt = blockIdx.x;
    const int b = blockIdx.y >> 4, h = blockIdx.y & 15;
    const int wm = warp * 16;

    const size_t qbase  = ((size_t)(b*LL + qt*128))*DD + (size_t)h*DHD;
    const size_t kvbase = ((size_t)(b*LL))*DD + (size_t)h*DHD;

    // prologue: Q + KV tile 0 -> one group
    #pragma unroll
    for (int t = 0; t < 4; t++) {
        int idx = t*256 + tid;
        int row = idx >> 3, seg = idx & 7;
        uint32_t off = SWZ128((uint32_t)(row*128 + seg*16));
        size_t go = qbase + (size_t)row*DD + seg*8;
        CP_ASYNC16(sb + off, q + go);
    }
    attn_issue_kv(sb + ATT_Q_BYTES, kh, kl, vh, vl, kvbase, tid);
    CP_COMMIT();

    float sO[8][4];
    #pragma unroll
    for (int j = 0; j < 8; j++)
        #pragma unroll
        for (int qq = 0; qq < 4; qq++) sO[j][qq] = 0.f;
    float mrow[2] = {-1e30f, -1e30f};
    float lrow[2] = {0.f, 0.f};

    const int arow  = (lane & 7) + ((lane >> 3) & 1) * 8;
    const int akoff = (lane >> 4) * 16;
    const int brow  = (lane & 7) + (lane >> 4) * 8;
    const int bkoff = ((lane >> 3) & 1) * 16;
    const int vgrp  = lane >> 3, vr = lane & 7;   // trans-ldsm addressing

    const int NT = LL / 64;   // 32 key tiles
    for (int kt = 0; kt < NT; kt++) {
        __syncthreads();
        if (kt + 1 < NT) {
            attn_issue_kv(sb + ATT_Q_BYTES + ((kt+1)&1)*ATT_KV_STAGE,
                          kh, kl, vh, vl, kvbase + (size_t)(kt+1)*64*DD, tid);
            CP_COMMIT();
            CP_WAIT(1);
        } else {
            CP_WAIT(0);
        }
        __syncthreads();

        uint32_t kvs = sb + ATT_Q_BYTES + (kt&1)*ATT_KV_STAGE;

        // ---- S = Q K^T (2-pass: Kh + Kl) ----
        float sS[8][4];
        #pragma unroll
        for (int j = 0; j < 8; j++)
            #pragma unroll
            for (int qq = 0; qq < 4; qq++) sS[j][qq] = 0.f;

        #pragma unroll
        for (int ks = 0; ks < 4; ks++) {
            uint32_t aq[4];
            uint32_t offa = SWZ128((uint32_t)((wm + arow)*128 + ks*32 + akoff));
            ldsm_x4(aq, sb + offa);
            #pragma unroll
            for (int g = 0; g < 4; g++) {
                uint32_t bh_[4], bl_[4];
                uint32_t offb = SWZ128((uint32_t)((g*16 + brow)*128 + ks*32 + bkoff));
                ldsm_x4(bh_, kvs + offb);
                ldsm_x4(bl_, kvs + 8192 + offb);
                mma16816(sS[2*g],   aq, bh_);
                mma16816(sS[2*g],   aq, bl_);
                mma16816(sS[2*g+1], aq, bh_ + 2);
                mma16816(sS[2*g+1], aq, bl_ + 2);
            }
        }

        // scale (faithful source bug: 1/sqrt(H) = 0.25)
        #pragma unroll
        for (int j = 0; j < 8; j++)
            #pragma unroll
            for (int qq = 0; qq < 4; qq++) sS[j][qq] *= 0.25f;

        // ---- online softmax (rows: rr=0 -> lane>>2, rr=1 -> +8) ----
        #pragma unroll
        for (int rr = 0; rr < 2; rr++) {
            float tm = -1e30f;
            #pragma unroll
            for (int j = 0; j < 8; j++) {
                tm = fmaxf(tm, sS[j][rr*2+0]);
                tm = fmaxf(tm, sS[j][rr*2+1]);
            }
            tm = fmaxf(tm, __shfl_xor_sync(0xffffffffu, tm, 1));
            tm = fmaxf(tm, __shfl_xor_sync(0xffffffffu, tm, 2));
            float mnew = fmaxf(mrow[rr], tm);
            float corr = __expf(mrow[rr] - mnew);
            mrow[rr] = mnew;
            float psum = 0.f;
            #pragma unroll
            for (int j = 0; j < 8; j++) {
                float p0 = __expf(sS[j][rr*2+0] - mnew);
                float p1 = __expf(sS[j][rr*2+1] - mnew);
                sS[j][rr*2+0] = p0; sS[j][rr*2+1] = p1;
                psum += p0 + p1;
            }
            psum += __shfl_xor_sync(0xffffffffu, psum, 1);
            psum += __shfl_xor_sync(0xffffffffu, psum, 2);
            lrow[rr] = lrow[rr]*corr + psum;
            #pragma unroll
            for (int j = 0; j < 8; j++) {
                sO[j][rr*2+0] *= corr;
                sO[j][rr*2+1] *= corr;
            }
        }

        // ---- pack P (A-fragments for PV, fp16) ----
        uint32_t pa[4][4];
        #pragma unroll
        for (int k = 0; k < 4; k++) {
            pa[k][0] = pack_hf2(sS[2*k][0],   sS[2*k][1]);
            pa[k][1] = pack_hf2(sS[2*k][2],   sS[2*k][3]);
            pa[k][2] = pack_hf2(sS[2*k+1][0], sS[2*k+1][1]);
            pa[k][3] = pack_hf2(sS[2*k+1][2], sS[2*k+1][3]);
        }

        // ---- O += P V (2-pass: Vh + Vl) ----
        #pragma unroll
        for (int ks = 0; ks < 4; ks++) {
            #pragma unroll
            for (int g = 0; g < 4; g++) {
                uint32_t bvh[4], bvl[4];
                int row = ks*16 + (vgrp & 1)*8 + vr;
                int colb = (g*16 + (vgrp >> 1)*8) * 2;
                uint32_t offv = SWZ128((uint32_t)(row*128 + colb));
                ldsm_x4_t(bvh, kvs + 16384 + offv);
                ldsm_x4_t(bvl, kvs + 24576 + offv);
                mma16816(sO[2*g],   pa[ks], bvh);
                mma16816(sO[2*g],   pa[ks], bvl);
                mma16816(sO[2*g+1], pa[ks], bvh + 2);
                mma16816(sO[2*g+1], pa[ks], bvl + 2);
            }
        }
    }

    // ---- epilogue: normalize + fp16 store ----
    #pragma unroll
    for (int rr = 0; rr < 2; rr++) {
        float inv = 1.0f / lrow[rr];
        int row = qt*128 + wm + rr*8 + (lane >> 2);
        size_t ob = ((size_t)(b*LL + row))*DD + (size_t)h*DHD + (lane & 3)*2;
        #pragma unroll
        for (int j = 0; j < 8; j++) {
            float v0 = sO[j][rr*2+0] * inv;
            float v1 = sO[j][rr*2+1] * inv;
            *(uint32_t*)(o + ob + j*8) = pack_hf2(v0, v1);
        }
    }
}

// ---------------- launcher ---------------------------------------------------
extern "C" void kernel_launch(void* const* d_in, const int* in_sizes, int n_in,
                              void* d_out, int out_size) {
    const float* x  = (const float*)d_in[0];
    const float* wq = (const float*)d_in[1];
    const float* bq = (const float*)d_in[2];
    const float* wk = (const float*)d_in[3];
    const float* bk = (const float*)d_in[4];
    const float* wv = (const float*)d_in[5];
    const float* bv = (const float*)d_in[6];
    const float* wo = (const float*)d_in[7];
    const float* bo = (const float*)d_in[8];
    const float* w1 = (const float*)d_in[9];
    const float* b1 = (const float*)d_in[10];
    const float* w2 = (const float*)d_in[11];
    const float* b2 = (const float*)d_in[12];
    float* out = (float*)d_out;

    cudaFuncSetAttribute((const void*)mm_gemm,
                         cudaFuncAttributeMaxDynamicSharedMemorySize, MMG_SMEM);
    cudaFuncSetAttribute((const void*)attn_tc,
                         cudaFuncAttributeMaxDynamicSharedMemorySize, ATT_SMEM);

    void *ph_, *pa, *pf, *pwh, *pwl;
    void *pqh, *pkh, *pkl, *pvh, *pvl, *po;
    cudaGetSymbolAddress(&ph_, g_h);
    cudaGetSymbolAddress(&pa,  g_a);
    cudaGetSymbolAddress(&pf,  g_f);
    cudaGetSymbolAddress(&pwh, g_wh);
    cudaGetSymbolAddress(&pwl, g_wl);
    cudaGetSymbolAddress(&pqh, g_qh);
    cudaGetSymbolAddress(&pkh, g_kh);
    cudaGetSymbolAddress(&pkl, g_kl);
    cudaGetSymbolAddress(&pvh, g_vh);
    cudaGetSymbolAddress(&pvl, g_vl);
    cudaGetSymbolAddress(&po,  g_o);
    float* h = (float*)ph_;
    __half* a  = (__half*)pa;
    __half* f  = (__half*)pf;
    __half* wh = (__half*)pwh;
    __half* wl = (__half*)pwl;
    __half* qh = (__half*)pqh;
    __half* kh = (__half*)pkh;
    __half* kl = (__half*)pkl;
    __half* vh = (__half*)pvh;
    __half* vl = (__half*)pvl;
    __half* o  = (__half*)po;

    dim3 gRed(1024, BB);
    dim3 gProj(DD/128,  MTOT/128);   // (8, 32)
    dim3 gFF1 (FFD/128, MTOT/128);   // (32, 32)
    dim3 gAtt (LL/128, BB*HH);       // (16, 32)

    // weight prep: split (hi/lo) for q/k/v/o, cast for w1/w2
    split_kernel<<<1024, 256>>>(wq, wh + WOFF_Q, wl + WOFF_Q, 262144);
    split_kernel<<<1024, 256>>>(wk, wh + WOFF_K, wl + WOFF_K, 262144);
    split_kernel<<<1024, 256>>>(wv, wh + WOFF_V, wl + WOFF_V, 262144);
    split_kernel<<<1024, 256>>>(wo, wh + WOFF_O, wl + WOFF_O, 262144);
    cast_kernel<<<4096, 256>>>(w1, wh + WOFF_1, 1048576);
    cast_kernel<<<4096, 256>>>(w2, wh + WOFF_2, 1048576);

    // LN1 -> fp16 activations
    ln_partial<<<gRed, 256>>>(x);
    ln_finalize<<<BB, 256>>>();
    ln_apply_f16<<<4096, 256>>>(x, a);
    // QKV projections (2-pass weights; Q single out, K/V hi/lo split outputs)
    mm_gemm<<<gProj, 256, MMG_SMEM>>>(a, wh + WOFF_Q, wl + WOFF_Q, bq, nullptr,
                                      nullptr, qh, nullptr, MTOT, DD, DD, 0);
    mm_gemm<<<gProj, 256, MMG_SMEM>>>(a, wh + WOFF_K, wl + WOFF_K, bk, nullptr,
                                      nullptr, kh, kl, MTOT, DD, DD, 0);
    mm_gemm<<<gProj, 256, MMG_SMEM>>>(a, wh + WOFF_V, wl + WOFF_V, bv, nullptr,
                                      nullptr, vh, vl, MTOT, DD, DD, 0);
    // tensor-core flash attention -> fp16 o
    attn_tc<<<gAtt, 256, ATT_SMEM>>>(qh, kh, kl, vh, vl, o);
    // output projection (2-pass weights) + residual(x) -> h (fp32)
    mm_gemm<<<gProj, 256, MMG_SMEM>>>(o, wh + WOFF_O, wl + WOFF_O, bo, x,
                                      h, nullptr, nullptr, MTOT, DD, DD, 0);
    // LN2 -> fp16
    ln_partial<<<gRed, 256>>>(h);
    ln_finalize<<<BB, 256>>>();
    ln_apply_f16<<<4096, 256>>>(h, a);
    // FFN1 (relu, single-pass weights) -> fp16 hidden
    mm_gemm<<<gFF1, 256, MMG_SMEM>>>(a, wh + WOFF_1, nullptr, b1, nullptr,
                                     nullptr, f, nullptr, MTOT, FFD, DD, 1);
    // FFN2 (single-pass weights) + residual(x) -> out (fp32)
    mm_gemm<<<gProj, 256, MMG_SMEM>>>(f, wh + WOFF_2, nullptr, b2, x,
                                      out, nullptr, nullptr, MTOT, DD, FFD, 0);
}

// round 16
// speedup vs baseline: 3.2554x; 1.1439x over previous
#include <cuda_runtime.h>
#include <cuda_fp16.h>
#include <cstdint>
#include <math.h>

#define BB  2
#define LL  2048
#define DD  1024
#define HH  16
#define DHD 64
#define FFD 4096
#define MTOT (BB*LL)          // 4096 rows

// ---------------- scratch (static device globals; no allocation) -------------
__device__ float g_h [(size_t)MTOT*DD];    // pre-LN2 tensor (o@wo+bo+x)
__device__ float g_psum[BB*1024];
__device__ float g_psq [BB*1024];
__device__ float g_mu  [BB];
__device__ float g_rstd[BB];

// fp16 buffers (all single-precision fp16 activations)
__device__ __half g_a [(size_t)MTOT*DD];     // LN output
__device__ __half g_f [(size_t)MTOT*FFD];    // FFN hidden
__device__ __half g_q [(size_t)MTOT*DD];
__device__ __half g_k [(size_t)MTOT*DD];
__device__ __half g_v [(size_t)MTOT*DD];
__device__ __half g_o [(size_t)MTOT*DD];     // attention output
// fp16 weights: hi for all, lo only for q/k/v/o (ffn weights single-pass)
#define WOFF_Q  ((size_t)0)
#define WOFF_K  ((size_t)1024*1024)
#define WOFF_V  ((size_t)2*1024*1024)
#define WOFF_O  ((size_t)3*1024*1024)
#define WOFF_1  ((size_t)4*1024*1024)
#define WOFF_2  ((size_t)8*1024*1024)
__device__ __half g_wh[(size_t)12*1024*1024];
__device__ __half g_wl[(size_t)4*1024*1024];

// ======================= PTX helpers (baseline ISA, no 'a' features) =========
__device__ __forceinline__ uint32_t smem_u32(const void* p) {
    uint32_t a;
    asm("{ .reg .u64 t; cvta.to.shared.u64 t, %1; cvt.u32.u64 %0, t; }" : "=r"(a) : "l"(p));
    return a;
}
#define SWZ128(o) ((o) ^ (((o) >> 3) & 0x70))

#define CP_ASYNC16(dst, src) \
    asm volatile("cp.async.cg.shared.global [%0], [%1], 16;" :: "r"(dst), "l"(src))
#define CP_COMMIT() asm volatile("cp.async.commit_group;" ::: "memory")
#define CP_WAIT(n)  asm volatile("cp.async.wait_group %0;" :: "n"(n) : "memory")

__device__ __forceinline__ void ldsm_x4(uint32_t* r, uint32_t addr) {
    asm volatile("ldmatrix.sync.aligned.m8n8.x4.shared.b16 {%0,%1,%2,%3}, [%4];"
        : "=r"(r[0]), "=r"(r[1]), "=r"(r[2]), "=r"(r[3]) : "r"(addr));
}
__device__ __forceinline__ void ldsm_x4_t(uint32_t* r, uint32_t addr) {
    asm volatile("ldmatrix.sync.aligned.m8n8.x4.trans.shared.b16 {%0,%1,%2,%3}, [%4];"
        : "=r"(r[0]), "=r"(r[1]), "=r"(r[2]), "=r"(r[3]) : "r"(addr));
}
__device__ __forceinline__ void mma16816(float* c, const uint32_t* a, const uint32_t* b) {
    asm volatile(
        "mma.sync.aligned.m16n8k16.row.col.f32.f16.f16.f32 "
        "{%0,%1,%2,%3}, {%4,%5,%6,%7}, {%8,%9}, {%0,%1,%2,%3};"
        : "+f"(c[0]), "+f"(c[1]), "+f"(c[2]), "+f"(c[3])
        : "r"(a[0]), "r"(a[1]), "r"(a[2]), "r"(a[3]), "r"(b[0]), "r"(b[1]));
}
// pack two fp32 -> half2 bits (lo = p0, hi = p1)
__device__ __forceinline__ uint32_t pack_hf2(float p0, float p1) {
    __half2 h = __floats2half2_rn(p0, p1);
    return *(uint32_t*)&h;
}

// ---------------- LayerNorm over (L,D) jointly per batch ---------------------
__global__ void ln_partial(const float* __restrict__ x) {
    int b = blockIdx.y, blk = blockIdx.x;
    const float4* xb = (const float4*)x + (size_t)b*(LL*DD/4) + (size_t)blk*512;
    float s = 0.f, sq = 0.f;
    for (int i = threadIdx.x; i < 512; i += 256) {
        float4 v = xb[i];
        s  += v.x + v.y + v.z + v.w;
        sq += v.x*v.x + v.y*v.y + v.z*v.z + v.w*v.w;
    }
    __shared__ float ss[256], ssq[256];
    ss[threadIdx.x] = s; ssq[threadIdx.x] = sq;
    __syncthreads();
    for (int st = 128; st > 0; st >>= 1) {
        if (threadIdx.x < st) { ss[threadIdx.x] += ss[threadIdx.x+st]; ssq[threadIdx.x] += ssq[threadIdx.x+st]; }
        __syncthreads();
    }
    if (threadIdx.x == 0) { g_psum[b*1024+blk] = ss[0]; g_psq[b*1024+blk] = ssq[0]; }
}

__global__ void ln_finalize() {
    int b = blockIdx.x, tid = threadIdx.x;
    float s = 0.f, sq = 0.f;
    for (int i = tid; i < 1024; i += 256) { s += g_psum[b*1024+i]; sq += g_psq[b*1024+i]; }
    __shared__ float ss[256], ssq[256];
    ss[tid] = s; ssq[tid] = sq;
    __syncthreads();
    for (int st = 128; st > 0; st >>= 1) {
        if (tid < st) { ss[tid] += ss[tid+st]; ssq[tid] += ssq[tid+st]; }
        __syncthreads();
    }
    if (tid == 0) {
        float n   = (float)LL * (float)DD;
        float mu  = ss[0] / n;
        float var = ssq[0] / n - mu*mu;
        g_mu[b]   = mu;
        g_rstd[b] = rsqrtf(var + 1e-5f);
    }
}

// normalize -> single fp16
__global__ void ln_apply_f16(const float* __restrict__ in, __half* __restrict__ out) {
    int i = blockIdx.x*256 + threadIdx.x;           // float4 index
    int b = (i >= (LL*DD/4)) ? 1 : 0;
    float mu = g_mu[b], r = g_rstd[b];
    float4 v = ((const float4*)in)[i];
    uint2 p;
    p.x = pack_hf2((v.x-mu)*r, (v.y-mu)*r);
    p.y = pack_hf2((v.z-mu)*r, (v.w-mu)*r);
    ((uint2*)out)[i] = p;
}

// split fp32 -> fp16 hi/lo (q/k/v/o weights)
__global__ void split_kernel(const float* __restrict__ in,
                             __half* __restrict__ hi, __half* __restrict__ lo, int n4) {
    int i = blockIdx.x*256 + threadIdx.x;
    if (i >= n4) return;
    float4 v = ((const float4*)in)[i];
    __half h0 = __float2half(v.x), h1 = __float2half(v.y);
    __half h2 = __float2half(v.z), h3 = __float2half(v.w);
    float l0 = v.x - __half2float(h0), l1 = v.y - __half2float(h1);
    float l2 = v.z - __half2float(h2), l3 = v.w - __half2float(h3);
    uint2 ph, pl;
    ph.x = ((uint32_t)__half_as_ushort(h1) << 16) | (uint32_t)__half_as_ushort(h0);
    ph.y = ((uint32_t)__half_as_ushort(h3) << 16) | (uint32_t)__half_as_ushort(h2);
    pl.x = pack_hf2(l0, l1);
    pl.y = pack_hf2(l2, l3);
    ((uint2*)hi)[i] = ph;
    ((uint2*)lo)[i] = pl;
}

// cast fp32 -> fp16 (ffn weights, single precision pass)
__global__ void cast_kernel(const float* __restrict__ in, __half* __restrict__ out, int n4) {
    int i = blockIdx.x*256 + threadIdx.x;
    if (i >= n4) return;
    float4 v = ((const float4*)in)[i];
    uint2 p;
    p.x = pack_hf2(v.x, v.y);
    p.y = pack_hf2(v.z, v.w);
    ((uint2*)out)[i] = p;
}

// =============== mma.sync GEMM: C[m,n] = sum_k A[m,k]*W[n,k] (+bias,resid,relu)
// CTA tile 128x128, K-chunk 64 fp16, 2-stage cp.async double buffer, 2 CTA/SM.
// A single fp16; W hi (+optional lo -> 2 MMA passes).
#define TILEB 16384                 // one 128x64 fp16 tile (128B rows)
#define STAGE_BYTES (3*TILEB)       // A, Bh, Bl
#define MMG_SMEM (2*STAGE_BYTES + 1024)

__device__ __forceinline__ void issue_chunk(
    uint32_t sslot,
    const __half* a0, const __half* b0, const __half* b1,
    int K, int k0, int tid)
{
    #pragma unroll
    for (int it = 0; it < 4; it++) {
        int idx = it*256 + tid;
        int row = idx >> 3, s = idx & 7;
        uint32_t off = SWZ128((uint32_t)(row*128 + s*16));
        size_t go = (size_t)row*K + k0 + s*8;
        CP_ASYNC16(sslot + off,            a0 + go);
        CP_ASYNC16(sslot + TILEB + off,    b0 + go);
        if (b1) CP_ASYNC16(sslot + 2*TILEB + off, b1 + go);
    }
}

__global__ __launch_bounds__(256, 2) void mm_gemm(
    const __half* __restrict__ A,
    const __half* __restrict__ Bh, const __half* __restrict__ Bl,
    const float* __restrict__ bias, const float* __restrict__ resid,
    float* __restrict__ C, __half* __restrict__ Chi,
    int M, int N, int K, int relu)
{
    extern __shared__ char smraw[];
    char* smb = (char*)(((uintptr_t)smraw + 1023) & ~(uintptr_t)1023);
    uint32_t sbase = smem_u32(smb);

    const int tid  = threadIdx.x;
    const int warp = tid >> 5, lane = tid & 31;
    const int m0 = blockIdx.y * 128, n0 = blockIdx.x * 128;
    const int wm = (warp >> 1) * 32;
    const int wn = (warp & 1) * 64;

    const __half* tA  = A  + (size_t)m0 * K;
    const __half* tB0 = Bh + (size_t)n0 * K;
    const __half* tB1 = Bl ? (Bl + (size_t)n0 * K) : (const __half*)nullptr;
    const bool twob = (Bl != nullptr);

    float acc[2][8][4];
    #pragma unroll
    for (int i = 0; i < 2; i++)
        #pragma unroll
        for (int j = 0; j < 8; j++)
            #pragma unroll
            for (int q = 0; q < 4; q++) acc[i][j][q] = 0.f;

    const int nch = K >> 6;
    issue_chunk(sbase, tA, tB0, tB1, K, 0, tid);
    CP_COMMIT();

    const int arow  = (lane & 7) + ((lane >> 3) & 1) * 8;
    const int akoff = (lane >> 4) * 16;
    const int brow  = (lane & 7) + (lane >> 4) * 8;
    const int bkoff = ((lane >> 3) & 1) * 16;

    for (int c = 0; c < nch; c++) {
        __syncthreads();            // all warps done reading the buffer we refill
        if (c + 1 < nch) {
            issue_chunk(sbase + ((c+1)&1)*STAGE_BYTES, tA, tB0, tB1, K, (c+1)*64, tid);
            CP_COMMIT();
            CP_WAIT(1);
        } else {
            CP_WAIT(0);
        }
        __syncthreads();

        uint32_t sl = sbase + (c & 1)*STAGE_BYTES;
        #pragma unroll
        for (int ks = 0; ks < 4; ks++) {
            uint32_t ah[2][4];
            #pragma unroll
            for (int mf = 0; mf < 2; mf++) {
                uint32_t off = SWZ128((uint32_t)((wm + mf*16 + arow)*128 + ks*32 + akoff));
                ldsm_x4(ah[mf], sl + off);
            }
            #pragma unroll
            for (int g = 0; g < 4; g++) {
                uint32_t bh[4];
                uint32_t off = SWZ128((uint32_t)((wn + g*16 + brow)*128 + ks*32 + bkoff));
                ldsm_x4(bh, sl + TILEB + off);
                if (twob) {
                    uint32_t bl[4];
                    ldsm_x4(bl, sl + 2*TILEB + off);
                    #pragma unroll
                    for (int mf = 0; mf < 2; mf++) {
                        mma16816(acc[mf][2*g],   ah[mf], bh);
                        mma16816(acc[mf][2*g],   ah[mf], bl);
                        mma16816(acc[mf][2*g+1], ah[mf], bh + 2);
                        mma16816(acc[mf][2*g+1], ah[mf], bl + 2);
                    }
                } else {
                    #pragma unroll
                    for (int mf = 0; mf < 2; mf++) {
                        mma16816(acc[mf][2*g],   ah[mf], bh);
                        mma16816(acc[mf][2*g+1], ah[mf], bh + 2);
                    }
                }
            }
        }
    }

    // epilogue
    const int rbase = m0 + wm + (lane >> 2);
    const int cbase = n0 + wn + (lane & 3) * 2;
    #pragma unroll
    for (int nf = 0; nf < 8; nf++) {
        const int col = cbase + nf*8;
        float2 bv = *(const float2*)(bias + col);
        #pragma unroll
        for (int mf = 0; mf < 2; mf++) {
            int r0 = rbase + mf*16;
            #pragma unroll
            for (int half_ = 0; half_ < 2; half_++) {
                int rr = r0 + half_*8;
                float vx = acc[mf][nf][half_*2+0] + bv.x;
                float vy = acc[mf][nf][half_*2+1] + bv.y;
                if (resid) {
                    float2 rv = *(const float2*)(resid + (size_t)rr*N + col);
                    vx += rv.x; vy += rv.y;
                }
                if (relu) { vx = fmaxf(vx, 0.f); vy = fmaxf(vy, 0.f); }
                if (Chi) {
                    *(uint32_t*)(Chi + (size_t)rr*N + col) = pack_hf2(vx, vy);
                } else {
                    float2 v2 = make_float2(vx, vy);
                    *(float2*)(C + (size_t)rr*N + col) = v2;
                }
            }
        }
    }
}

// ======= tensor-core flash attention: O = softmax(Q K^T * 0.25) V ============
// CTA: 128 q-rows of one (b,h). 8 warps x 16 rows. Key tiles of 64.
// Single-pass fp16 Q,K,V; fp32 softmax; P fp16.
// smem: Q 16KB + 2 stages x (k,v) 16KB = 48KB.
#define ATT_Q_BYTES 16384
#define ATT_KV_STAGE 16384
#define ATT_SMEM (ATT_Q_BYTES + 2*ATT_KV_STAGE)

__device__ __forceinline__ void attn_issue_kv(
    uint32_t kvs,
    const __half* k, const __half* v,
    size_t gbase, int tid)
{
    #pragma unroll
    for (int t = 0; t < 2; t++) {
        int idx = t*256 + tid;
        int row = idx >> 3, seg = idx & 7;
        uint32_t off = SWZ128((uint32_t)(row*128 + seg*16));
        size_t go = gbase + (size_t)row*DD + seg*8;
        CP_ASYNC16(kvs + off,         k + go);
        CP_ASYNC16(kvs + 8192 + off,  v + go);
    }
}

__global__ __launch_bounds__(256) void attn_tc(
    const __half* __restrict__ q,
    const __half* __restrict__ k,
    const __half* __restrict__ v,
    __half* __restrict__ o)
{
    extern __shared__ char smraw[];
    uint32_t sb = smem_u32(smraw);
    const int tid = threadIdx.x, warp = tid >> 5, lane = tid & 31;
    const int qt = blockIdx.x;
    const int b = blockIdx.y >> 4, h = blockIdx.y & 15;
    const int wm = warp * 16;

    const size_t qbase  = ((size_t)(b*LL + qt*128))*DD + (size_t)h*DHD;
    const size_t kvbase = ((size_t)(b*LL))*DD + (size_t)h*DHD;

    // prologue: Q + KV tile 0 -> one group
    #pragma unroll
    for (int t = 0; t < 4; t++) {
        int idx = t*256 + tid;
        int row = idx >> 3, seg = idx & 7;
        uint32_t off = SWZ128((uint32_t)(row*128 + seg*16));
        size_t go = qbase + (size_t)row*DD + seg*8;
        CP_ASYNC16(sb + off, q + go);
    }
    attn_issue_kv(sb + ATT_Q_BYTES, k, v, kvbase, tid);
    CP_COMMIT();

    float sO[8][4];
    #pragma unroll
    for (int j = 0; j < 8; j++)
        #pragma unroll
        for (int qq = 0; qq < 4; qq++) sO[j][qq] = 0.f;
    float mrow[2] = {-1e30f, -1e30f};
    float lrow[2] = {0.f, 0.f};

    const int arow  = (lane & 7) + ((lane >> 3) & 1) * 8;
    const int akoff = (lane >> 4) * 16;
    const int brow  = (lane & 7) + (lane >> 4) * 8;
    const int bkoff = ((lane >> 3) & 1) * 16;
    const int vgrp  = lane >> 3, vr = lane & 7;   // trans-ldsm addressing

    const int NT = LL / 64;   // 32 key tiles
    for (int kt = 0; kt < NT; kt++) {
        __syncthreads();
        if (kt + 1 < NT) {
            attn_issue_kv(sb + ATT_Q_BYTES + ((kt+1)&1)*ATT_KV_STAGE,
                          k, v, kvbase + (size_t)(kt+1)*64*DD, tid);
            CP_COMMIT();
            CP_WAIT(1);
        } else {
            CP_WAIT(0);
        }
        __syncthreads();

        uint32_t kvs = sb + ATT_Q_BYTES + (kt&1)*ATT_KV_STAGE;

        // ---- S = Q K^T ----
        float sS[8][4];
        #pragma unroll
        for (int j = 0; j < 8; j++)
            #pragma unroll
            for (int qq = 0; qq < 4; qq++) sS[j][qq] = 0.f;

        #pragma unroll
        for (int ks = 0; ks < 4; ks++) {
            uint32_t aq[4];
            uint32_t offa = SWZ128((uint32_t)((wm + arow)*128 + ks*32 + akoff));
            ldsm_x4(aq, sb + offa);
            #pragma unroll
            for (int g = 0; g < 4; g++) {
                uint32_t bh_[4];
                uint32_t offb = SWZ128((uint32_t)((g*16 + brow)*128 + ks*32 + bkoff));
                ldsm_x4(bh_, kvs + offb);
                mma16816(sS[2*g],   aq, bh_);
                mma16816(sS[2*g+1], aq, bh_ + 2);
            }
        }

        // scale (faithful source bug: 1/sqrt(H) = 0.25)
        #pragma unroll
        for (int j = 0; j < 8; j++)
            #pragma unroll
            for (int qq = 0; qq < 4; qq++) sS[j][qq] *= 0.25f;

        // ---- online softmax (rows: rr=0 -> lane>>2, rr=1 -> +8) ----
        #pragma unroll
        for (int rr = 0; rr < 2; rr++) {
            float tm = -1e30f;
            #pragma unroll
            for (int j = 0; j < 8; j++) {
                tm = fmaxf(tm, sS[j][rr*2+0]);
                tm = fmaxf(tm, sS[j][rr*2+1]);
            }
            tm = fmaxf(tm, __shfl_xor_sync(0xffffffffu, tm, 1));
            tm = fmaxf(tm, __shfl_xor_sync(0xffffffffu, tm, 2));
            float mnew = fmaxf(mrow[rr], tm);
            float corr = __expf(mrow[rr] - mnew);
            mrow[rr] = mnew;
            float psum = 0.f;
            #pragma unroll
            for (int j = 0; j < 8; j++) {
                float p0 = __expf(sS[j][rr*2+0] - mnew);
                float p1 = __expf(sS[j][rr*2+1] - mnew);
                sS[j][rr*2+0] = p0; sS[j][rr*2+1] = p1;
                psum += p0 + p1;
            }
            psum += __shfl_xor_sync(0xffffffffu, psum, 1);
            psum += __shfl_xor_sync(0xffffffffu, psum, 2);
            lrow[rr] = lrow[rr]*corr + psum;
            #pragma unroll
            for (int j = 0; j < 8; j++) {
                sO[j][rr*2+0] *= corr;
                sO[j][rr*2+1] *= corr;
            }
        }

        // ---- pack P (A-fragments for PV, fp16) ----
        uint32_t pa[4][4];
        #pragma unroll
        for (int kk = 0; kk < 4; kk++) {
            pa[kk][0] = pack_hf2(sS[2*kk][0],   sS[2*kk][1]);
            pa[kk][1] = pack_hf2(sS[2*kk][2],   sS[2*kk][3]);
            pa[kk][2] = pack_hf2(sS[2*kk+1][0], sS[2*kk+1][1]);
            pa[kk][3] = pack_hf2(sS[2*kk+1][2], sS[2*kk+1][3]);
        }

        // ---- O += P V ----
        #pragma unroll
        for (int ks = 0; ks < 4; ks++) {
            #pragma unroll
            for (int g = 0; g < 4; g++) {
                uint32_t bv_[4];
                int row = ks*16 + (vgrp & 1)*8 + vr;
                int colb = (g*16 + (vgrp >> 1)*8) * 2;
                uint32_t offv = SWZ128((uint32_t)(row*128 + colb));
                ldsm_x4_t(bv_, kvs + 8192 + offv);
                mma16816(sO[2*g],   pa[ks], bv_);
                mma16816(sO[2*g+1], pa[ks], bv_ + 2);
            }
        }
    }

    // ---- epilogue: normalize + fp16 store ----
    #pragma unroll
    for (int rr = 0; rr < 2; rr++) {
        float inv = 1.0f / lrow[rr];
        int row = qt*128 + wm + rr*8 + (lane >> 2);
        size_t ob = ((size_t)(b*LL + row))*DD + (size_t)h*DHD + (lane & 3)*2;
        #pragma unroll
        for (int j = 0; j < 8; j++) {
            float v0 = sO[j][rr*2+0] * inv;
            float v1 = sO[j][rr*2+1] * inv;
            *(uint32_t*)(o + ob + j*8) = pack_hf2(v0, v1);
        }
    }
}

// ---------------- launcher ---------------------------------------------------
extern "C" void kernel_launch(void* const* d_in, const int* in_sizes, int n_in,
                              void* d_out, int out_size) {
    const float* x  = (const float*)d_in[0];
    const float* wq = (const float*)d_in[1];
    const float* bq = (const float*)d_in[2];
    const float* wk = (const float*)d_in[3];
    const float* bk = (const float*)d_in[4];
    const float* wv = (const float*)d_in[5];
    const float* bv = (const float*)d_in[6];
    const float* wo = (const float*)d_in[7];
    const float* bo = (const float*)d_in[8];
    const float* w1 = (const float*)d_in[9];
    const float* b1 = (const float*)d_in[10];
    const float* w2 = (const float*)d_in[11];
    const float* b2 = (const float*)d_in[12];
    float* out = (float*)d_out;

    cudaFuncSetAttribute((const void*)mm_gemm,
                         cudaFuncAttributeMaxDynamicSharedMemorySize, MMG_SMEM);
    cudaFuncSetAttribute((const void*)attn_tc,
                         cudaFuncAttributeMaxDynamicSharedMemorySize, ATT_SMEM);

    void *ph_, *pa, *pf, *pwh, *pwl, *pq, *pk, *pv, *po;
    cudaGetSymbolAddress(&ph_, g_h);
    cudaGetSymbolAddress(&pa,  g_a);
    cudaGetSymbolAddress(&pf,  g_f);
    cudaGetSymbolAddress(&pwh, g_wh);
    cudaGetSymbolAddress(&pwl, g_wl);
    cudaGetSymbolAddress(&pq,  g_q);
    cudaGetSymbolAddress(&pk,  g_k);
    cudaGetSymbolAddress(&pv,  g_v);
    cudaGetSymbolAddress(&po,  g_o);
    float* h = (float*)ph_;
    __half* a  = (__half*)pa;
    __half* f  = (__half*)pf;
    __half* wh = (__half*)pwh;
    __half* wl = (__half*)pwl;
    __half* q  = (__half*)pq;
    __half* k  = (__half*)pk;
    __half* v  = (__half*)pv;
    __half* o  = (__half*)po;

    dim3 gRed(1024, BB);
    dim3 gProj(DD/128,  MTOT/128);   // (8, 32)
    dim3 gFF1 (FFD/128, MTOT/128);   // (32, 32)
    dim3 gAtt (LL/128, BB*HH);       // (16, 32)

    // weight prep: split (hi/lo) for q/k/v/o, cast for w1/w2
    split_kernel<<<1024, 256>>>(wq, wh + WOFF_Q, wl + WOFF_Q, 262144);
    split_kernel<<<1024, 256>>>(wk, wh + WOFF_K, wl + WOFF_K, 262144);
    split_kernel<<<1024, 256>>>(wv, wh + WOFF_V, wl + WOFF_V, 262144);
    split_kernel<<<1024, 256>>>(wo, wh + WOFF_O, wl + WOFF_O, 262144);
    cast_kernel<<<4096, 256>>>(w1, wh + WOFF_1, 1048576);
    cast_kernel<<<4096, 256>>>(w2, wh + WOFF_2, 1048576);

    // LN1 -> fp16 activations
    ln_partial<<<gRed, 256>>>(x);
    ln_finalize<<<BB, 256>>>();
    ln_apply_f16<<<4096, 256>>>(x, a);
    // QKV projections (2-pass weights; single fp16 outputs)
    mm_gemm<<<gProj, 256, MMG_SMEM>>>(a, wh + WOFF_Q, wl + WOFF_Q, bq, nullptr,
                                      nullptr, q, MTOT, DD, DD, 0);
    mm_gemm<<<gProj, 256, MMG_SMEM>>>(a, wh + WOFF_K, wl + WOFF_K, bk, nullptr,
                                      nullptr, k, MTOT, DD, DD, 0);
    mm_gemm<<<gProj, 256, MMG_SMEM>>>(a, wh + WOFF_V, wl + WOFF_V, bv, nullptr,
                                      nullptr, v, MTOT, DD, DD, 0);
    // tensor-core flash attention (single-pass fp16) -> fp16 o
    attn_tc<<<gAtt, 256, ATT_SMEM>>>(q, k, v, o);
    // output projection (2-pass weights) + residual(x) -> h (fp32)
    mm_gemm<<<gProj, 256, MMG_SMEM>>>(o, wh + WOFF_O, wl + WOFF_O, bo, x,
                                      h, nullptr, MTOT, DD, DD, 0);
    // LN2 -> fp16
    ln_partial<<<gRed, 256>>>(h);
    ln_finalize<<<BB, 256>>>();
    ln_apply_f16<<<4096, 256>>>(h, a);
    // FFN1 (relu, single-pass weights) -> fp16 hidden
    mm_gemm<<<gFF1, 256, MMG_SMEM>>>(a, wh + WOFF_1, nullptr, b1, nullptr,
                                     nullptr, f, MTOT, FFD, DD, 1);
    // FFN2 (single-pass weights) + residual(x) -> out (fp32)
    mm_gemm<<<gProj, 256, MMG_SMEM>>>(f, wh + WOFF_2, nullptr, b2, x,
                                      out, nullptr, MTOT, DD, FFD, 0);
}